// round 14
// baseline (speedup 1.0000x reference)
#include <cuda_runtime.h>
#include <math.h>
#include <stdint.h>

// Problem constants (fixed by the reference)
#define BSZ   8
#define CDIM  256
#define NDIM  1024          // 32*32
#define MROWS 8192          // NDIM*BSZ
#define NHEAD 8
#define HIDD  128
#define FFD   512
#define NHYP  3
#define HC    2048          // NHEAD*CDIM
#define NLR   4096          // fused Wl|Wr output width
#define NEG   0.2f
#define EPSLN 1e-5f

// ---------------------------------------------------------------------------
// Static scratch (no allocations allowed)
// ---------------------------------------------------------------------------
__device__ float g_node[MROWS * CDIM];
__device__ float g_adj [MROWS * CDIM];
__device__ float g_orig[MROWS * CDIM];
__device__ float g_tmp [MROWS * CDIM];
__device__ float g_tmp2[2 * MROWS * CDIM];     // GCN GEMM outs: z0=conf, z1=adj
__device__ float g_xlr [(size_t)MROWS * NLR];  // SINGLE hyp buffer, reused (L2-hot)
__device__ float g_blr [NHYP * NLR];

// bf16 (bit-pattern uint16) hi/lo activation buffers (row-major [M][K])
__device__ uint16_t bX0h [MROWS * CDIM], bX0l [MROWS * CDIM];
__device__ uint16_t bNodeh[MROWS * CDIM], bNodel[MROWS * CDIM];
__device__ uint16_t bHidh[MROWS * FFD],  bHidl[MROWS * FFD];
__device__ uint16_t bGateh[2 * MROWS * CDIM], bGatel[2 * MROWS * CDIM]; // z0=xc, z1=xa
__device__ uint16_t bConfh[MROWS * CDIM], bConfl[MROWS * CDIM];
__device__ uint16_t bOrigh[MROWS * CDIM], bOrigl[MROWS * CDIM];
__device__ uint16_t bHid3h[NHYP * MROWS * HIDD], bHid3l[NHYP * MROWS * HIDD];
__device__ uint16_t bFeat3h[NHYP * MROWS * CDIM], bFeat3l[NHYP * MROWS * CDIM];

// weight hi/lo buffers, stored [K][N] N-major (GEMM B operand)
__device__ uint16_t wWph [CDIM*CDIM],  wWpl [CDIM*CDIM];
__device__ uint16_t wWm1h[CDIM*HIDD],  wWm1l[CDIM*HIDD];
__device__ uint16_t wWm2h[HIDD*CDIM],  wWm2l[HIDD*CDIM];
__device__ uint16_t wGh  [2*CDIM*CDIM], wGl [2*CDIM*CDIM];      // z0=Wgcc, z1=Wgca
__device__ uint16_t wWi1h[NHYP*CDIM*HIDD], wWi1l[NHYP*CDIM*HIDD];
__device__ uint16_t wWi2h[NHYP*HIDD*CDIM], wWi2l[NHYP*HIDD*CDIM];
__device__ uint16_t wLRh [NHYP*(size_t)CDIM*NLR], wLRl[NHYP*(size_t)CDIM*NLR];
__device__ uint16_t wWf1h[CDIM*FFD],   wWf1l[CDIM*FFD];
__device__ uint16_t wWf2h[FFD*CDIM],   wWf2l[FFD*CDIM];

// ---------------------------------------------------------------------------
// bf16 split helpers
// ---------------------------------------------------------------------------
__device__ __forceinline__ uint32_t bf16_rn(float f)
{
    uint32_t u = __float_as_uint(f);
    return (u + 0x7FFFu + ((u >> 16) & 1u)) >> 16;
}
__device__ __forceinline__ void bf16_split(float f, uint32_t& h, uint32_t& l)
{
    h = bf16_rn(f);
    float rem = f - __uint_as_float(h << 16);
    l = bf16_rn(rem);
}
__device__ __forceinline__ void store_pair(uint16_t* hi, uint16_t* lo, size_t o,
                                           float v0, float v1)
{
    uint32_t h0, l0, h1, l1;
    bf16_split(v0, h0, l0);
    bf16_split(v1, h1, l1);
    *(uint32_t*)&hi[o] = h0 | (h1 << 16);
    *(uint32_t*)&lo[o] = l0 | (l1 << 16);
}

// ---------------------------------------------------------------------------
// ALL weight conversions in ONE launch (job table by value, blockIdx.y = job)
// ---------------------------------------------------------------------------
#define NJOBS 13
struct ConvJob {
    const float* src;
    uint16_t *hi, *lo;
    int N, LD, off, n4;
};
struct ConvJobs { ConvJob j[NJOBS]; };

__global__ void convert_all_k(ConvJobs jobs)
{
    ConvJob jb = jobs.j[blockIdx.y];
    int i = blockIdx.x * blockDim.x + threadIdx.x;
    if (i >= jb.n4) return;
    int e = i * 4;
    int k = e / jb.N, n = e - k * jb.N;
    float4 q = *(const float4*)(jb.src + e);
    uint32_t h0,h1,h2,h3,l0,l1,l2,l3;
    bf16_split(q.x,h0,l0); bf16_split(q.y,h1,l1);
    bf16_split(q.z,h2,l2); bf16_split(q.w,h3,l3);
    size_t d = (size_t)k * jb.LD + jb.off + n;
    *(uint2*)(jb.hi + d) = make_uint2(h0 | (h1 << 16), h2 | (h3 << 16));
    *(uint2*)(jb.lo + d) = make_uint2(l0 | (l1 << 16), l2 | (l3 << 16));
}

// blr[z][0:HC)=bl[z], blr[z][HC:NLR)=br[z]
__global__ void blr_fill_k(const float* __restrict__ bl, const float* __restrict__ br,
                           float* __restrict__ blr)
{
    int z = blockIdx.x;
    for (int c = threadIdx.x; c < NLR; c += blockDim.x)
        blr[(size_t)z * NLR + c] = (c < HC) ? bl[(size_t)z * HC + c]
                                            : br[(size_t)z * HC + c - HC];
}

// ---------------------------------------------------------------------------
// Transpose: x[B,C,N] -> X0[(n*B+b), C] as bf16 hi/lo
// ---------------------------------------------------------------------------
__global__ void transpose_in_k(const float* __restrict__ x,
                               uint16_t* __restrict__ X0h, uint16_t* __restrict__ X0l)
{
    __shared__ float s[32][33];
    int b  = blockIdx.z;
    int c0 = blockIdx.y * 32;
    int n0 = blockIdx.x * 32;
    int tx = threadIdx.x, ty = threadIdx.y;
    s[ty][tx] = x[((size_t)b * CDIM + (c0 + ty)) * NDIM + n0 + tx];
    __syncthreads();
    float v = s[tx][ty];
    uint32_t h, l;
    bf16_split(v, h, l);
    size_t o = ((size_t)(n0 + ty) * BSZ + b) * CDIM + c0 + tx;
    X0h[o] = (uint16_t)h;
    X0l[o] = (uint16_t)l;
}

// ---------------------------------------------------------------------------
// mma.sync tensor-core GEMM, templated BM (64 default; 128 for the LR GEMM
// to cut L2 tile traffic). BN=128, BK=32, 2-stage cp.async, z-batched.
// 3-term split: AhBh + AhBl + AlBh, fp32 accumulate.
// act: 0 fp32(+res), 1 relu->bf16, 2 gate->(C=sig*res, C2=(1-sig)*res),
//      3 fp32+bf16, 4 (bias+res)->bf16
// ---------------------------------------------------------------------------
__device__ __forceinline__ uint32_t sptr(const void* p)
{
    return (uint32_t)__cvta_generic_to_shared(p);
}
__device__ __forceinline__ void cp16_s(uint32_t dst, const void* src)
{
    asm volatile("cp.async.cg.shared.global [%0], [%1], 16;" :: "r"(dst), "l"(src));
}
__device__ __forceinline__ void ldsm4(uint32_t* r, uint32_t addr)
{
    asm volatile("ldmatrix.sync.aligned.m8n8.x4.shared.b16 {%0,%1,%2,%3}, [%4];"
                 : "=r"(r[0]), "=r"(r[1]), "=r"(r[2]), "=r"(r[3]) : "r"(addr));
}
__device__ __forceinline__ void ldsm4t(uint32_t* r, uint32_t addr)
{
    asm volatile("ldmatrix.sync.aligned.m8n8.x4.trans.shared.b16 {%0,%1,%2,%3}, [%4];"
                 : "=r"(r[0]), "=r"(r[1]), "=r"(r[2]), "=r"(r[3]) : "r"(addr));
}
__device__ __forceinline__ void mma16816(float* c, const uint32_t* a, uint32_t b0, uint32_t b1)
{
    asm volatile(
        "mma.sync.aligned.m16n8k16.row.col.f32.bf16.bf16.f32 "
        "{%0,%1,%2,%3}, {%4,%5,%6,%7}, {%8,%9}, {%0,%1,%2,%3};"
        : "+f"(c[0]), "+f"(c[1]), "+f"(c[2]), "+f"(c[3])
        : "r"(a[0]), "r"(a[1]), "r"(a[2]), "r"(a[3]), "r"(b0), "r"(b1));
}

#define GAP  40                       // A smem pitch (elems): 80B rows, conflict-free
#define GBP  136                      // B smem pitch (elems): 272B rows, conflict-free
#define B_SZE (32 * GBP)              // 4352 elems per B array per stage

template<int BM>
__global__ __launch_bounds__(256, (BM == 64) ? 3 : 2)
void gemm_k(const uint16_t* __restrict__ Ah, const uint16_t* __restrict__ Al,
            const uint16_t* __restrict__ Bh, const uint16_t* __restrict__ Bl,
            const float* __restrict__ bias, const float* __restrict__ res,
            float* __restrict__ C,
            uint16_t* __restrict__ Chi, uint16_t* __restrict__ Clo,
            uint16_t* __restrict__ C2hi, uint16_t* __restrict__ C2lo,
            int M, int N, int K, int ldb, int act,
            size_t zA, size_t zB, size_t zBias, size_t zC, size_t zRes)
{
    constexpr int WARPS_M = BM / 32;          // 2 or 4
    constexpr int WARPS_N = 8 / WARPS_M;      // 4 or 2
    constexpr int WN  = 128 / WARPS_N;        // 32 or 64
    constexpr int NF  = WN / 8;               // 4 or 8
    constexpr int NB  = WN / 16;              // 2 or 4
    constexpr int ASZ = BM * GAP;
    constexpr int STG = 2 * ASZ + 2 * B_SZE;  // stage elems
    constexpr int ACH = BM * 4;               // 16B chunks per A array
    constexpr int AV  = (ACH + 255) / 256;

    extern __shared__ __align__(16) uint16_t sm[];
    int z = blockIdx.z;
    Ah += z * zA; Al += z * zA;
    Bh += z * zB; Bl += z * zB;
    if (bias) bias += z * zBias;
    if (res)  res  += z * zRes;
    if (C)    C    += z * zC;
    if (Chi)  { Chi  += z * zC; Clo  += z * zC; }
    if (C2hi) { C2hi += z * zC; C2lo += z * zC; }

    int tid = threadIdx.x, wid = tid >> 5, lane = tid & 31;
    int wm = wid % WARPS_M, wn = wid / WARPS_M;
    int m0 = blockIdx.y * BM, n0 = blockIdx.x * 128;

    float acc[2][NF][4] = {};

    int a_row  = wm * 32 + (lane & 15);
    int a_koff = (lane >> 4) * 8;
    int b_k    = (lane & 7) + (lane & 8);
    int b_n    = wn * WN + ((lane & 16) >> 1);

    uint32_t smb = sptr(sm);

    auto load_stage = [&](int kt, int st) {
        uint32_t base = smb + st * (STG * 2);
        int kg = kt * 32;
        #pragma unroll
        for (int v = 0; v < AV; v++) {
            int idx = tid + v * 256;
            if (ACH >= 256 || idx < ACH) {
                int row = idx >> 2, kc = (idx & 3) * 8;
                size_t ga = (size_t)(m0 + row) * K + kg + kc;
                uint32_t da = base + (row * GAP + kc) * 2;
                cp16_s(da,           Ah + ga);
                cp16_s(da + ASZ * 2, Al + ga);
            }
        }
        #pragma unroll
        for (int v = 0; v < 2; v++) {
            int idx = tid + v * 256;
            int brow = idx >> 4, bnc = (idx & 15) * 8;
            size_t gb = (size_t)(kg + brow) * ldb + n0 + bnc;
            uint32_t db = base + 2 * ASZ * 2 + (brow * GBP + bnc) * 2;
            cp16_s(db,             Bh + gb);
            cp16_s(db + B_SZE * 2, Bl + gb);
        }
    };

    int KT = K / 32;
    load_stage(0, 0);
    asm volatile("cp.async.commit_group;");

    int buf = 0;
    for (int kt = 0; kt < KT; kt++) {
        if (kt + 1 < KT) {
            load_stage(kt + 1, buf ^ 1);
            asm volatile("cp.async.commit_group;");
            asm volatile("cp.async.wait_group 1;");
        } else {
            asm volatile("cp.async.wait_group 0;");
        }
        __syncthreads();

        uint32_t pAh = smb + buf * (STG * 2);
        uint32_t pAl = pAh + ASZ * 2;
        uint32_t pBh = pAh + 2 * ASZ * 2;
        uint32_t pBl = pBh + B_SZE * 2;

        #pragma unroll
        for (int ks = 0; ks < 2; ks++) {
            uint32_t ah[2][4], al[2][4];
            #pragma unroll
            for (int mf = 0; mf < 2; mf++) {
                uint32_t off = ((a_row + mf * 16) * GAP + ks * 16 + a_koff) * 2;
                ldsm4(ah[mf], pAh + off);
                ldsm4(al[mf], pAl + off);
            }
            #pragma unroll
            for (int nb = 0; nb < NB; nb++) {
                uint32_t bh[4], bl[4];
                uint32_t boff = ((ks * 16 + b_k) * GBP + b_n + nb * 16) * 2;
                ldsm4t(bh, pBh + boff);
                ldsm4t(bl, pBl + boff);
                #pragma unroll
                for (int mf = 0; mf < 2; mf++) {
                    mma16816(acc[mf][2*nb],   ah[mf], bh[0], bh[1]);
                    mma16816(acc[mf][2*nb],   ah[mf], bl[0], bl[1]);
                    mma16816(acc[mf][2*nb],   al[mf], bh[0], bh[1]);
                    mma16816(acc[mf][2*nb+1], ah[mf], bh[2], bh[3]);
                    mma16816(acc[mf][2*nb+1], ah[mf], bl[2], bl[3]);
                    mma16816(acc[mf][2*nb+1], al[mf], bh[2], bh[3]);
                }
            }
        }
        __syncthreads();
        buf ^= 1;
    }

    // ---- epilogue
    int gr = lane >> 2, gc = (lane & 3) * 2;
    #pragma unroll
    for (int mf = 0; mf < 2; mf++) {
        #pragma unroll
        for (int nf = 0; nf < NF; nf++) {
            int n = n0 + wn * WN + nf * 8 + gc;
            #pragma unroll
            for (int half = 0; half < 2; half++) {
                int m = m0 + wm * 32 + mf * 16 + gr + half * 8;
                size_t o = (size_t)m * N + n;
                float v0 = acc[mf][nf][2*half + 0];
                float v1 = acc[mf][nf][2*half + 1];
                if (bias) { v0 += __ldg(&bias[n]); v1 += __ldg(&bias[n + 1]); }
                if (act == 0) {
                    if (res) { float2 rr = *(const float2*)&res[o]; v0 += rr.x; v1 += rr.y; }
                    *(float2*)&C[o] = make_float2(v0, v1);
                } else if (act == 1) {
                    store_pair(Chi, Clo, o, fmaxf(v0, 0.f), fmaxf(v1, 0.f));
                } else if (act == 2) {
                    float2 nd = *(const float2*)&res[o];
                    float s0 = 1.f / (1.f + expf(-v0));
                    float s1 = 1.f / (1.f + expf(-v1));
                    store_pair(Chi,  Clo,  o, s0 * nd.x, s1 * nd.y);
                    store_pair(C2hi, C2lo, o, (1.f - s0) * nd.x, (1.f - s1) * nd.y);
                } else if (act == 3) {
                    *(float2*)&C[o] = make_float2(v0, v1);
                    store_pair(Chi, Clo, o, v0, v1);
                } else { // act == 4
                    float2 rr = *(const float2*)&res[o];
                    store_pair(Chi, Clo, o, v0 + rr.x, v1 + rr.y);
                }
            }
        }
    }
}

// ---------------------------------------------------------------------------
// Block-wide sum over 256 threads
// ---------------------------------------------------------------------------
__device__ __forceinline__ float bsum256(float v)
{
    __shared__ float s[256];
    int t = threadIdx.x;
    s[t] = v; __syncthreads();
    #pragma unroll
    for (int o = 128; o > 0; o >>= 1) {
        if (t < o) s[t] += s[t + o];
        __syncthreads();
    }
    float r = s[0];
    __syncthreads();
    return r;
}

__device__ __forceinline__ float grid_deg(int i, int j)
{
    return 1.f + (i > 0) + (i < 31) + (j > 0) + (j < 31);
}

// ---------------------------------------------------------------------------
// Fused GCN aggregation + bias + LayerNorm.
// ---------------------------------------------------------------------------
__global__ __launch_bounds__(256)
void gcn_ln_k(const float* __restrict__ hw, const float* __restrict__ bg,
              const float* __restrict__ gamma, const float* __restrict__ beta,
              float* __restrict__ out_f32,
              uint16_t* __restrict__ out_hi, uint16_t* __restrict__ out_lo,
              const float* __restrict__ addin, float* __restrict__ out2_f32,
              uint16_t* __restrict__ out2_hi, uint16_t* __restrict__ out2_lo)
{
    int r = blockIdx.x;
    int n = r >> 3, b = r & 7;
    int i = n >> 5, j = n & 31;
    float degn = grid_deg(i, j);

    int   nbr[5];
    float nrm[5];
    nbr[0] = n;                       nrm[0] = 1.f / degn;
    nbr[1] = (i > 0)  ? n - 32 : n;
    nbr[2] = (i < 31) ? n + 32 : n;
    nbr[3] = (j > 0)  ? n - 1  : n;
    nbr[4] = (j < 31) ? n + 1  : n;
    bool vld[5] = { true, i > 0, i < 31, j > 0, j < 31 };
    #pragma unroll
    for (int t = 1; t < 5; t++) {
        int m = nbr[t];
        float degm = grid_deg(m >> 5, m & 31);
        nrm[t] = vld[t] ? rsqrtf(degm * degn) : 0.f;
    }

    int c = threadIdx.x;
    float acc = bg[c];
    #pragma unroll
    for (int t = 0; t < 5; t++)
        acc += nrm[t] * hw[((size_t)nbr[t] * BSZ + b) * CDIM + c];

    float mean = bsum256(acc) * (1.f / CDIM);
    float d = acc - mean;
    float var = bsum256(d * d) * (1.f / CDIM);
    float o = d * rsqrtf(var + EPSLN) * gamma[c] + beta[c];
    size_t idx = (size_t)r * CDIM + c;

    if (out_f32) out_f32[idx] = o;
    if (out_hi) {
        uint32_t h, l; bf16_split(o, h, l);
        out_hi[idx] = (uint16_t)h; out_lo[idx] = (uint16_t)l;
    }
    if (addin) {
        float o2 = o + addin[idx];
        out2_f32[idx] = o2;
        uint32_t h, l; bf16_split(o2, h, l);
        out2_hi[idx] = (uint16_t)h; out2_lo[idx] = (uint16_t)l;
    }
}

// ---------------------------------------------------------------------------
// Final residual LayerNorm, writing image layout out[b,c,n]
// ---------------------------------------------------------------------------
__global__ __launch_bounds__(256)
void ln_out_k(const float* __restrict__ in, const float* __restrict__ gamma,
              const float* __restrict__ beta, float* __restrict__ outp)
{
    int r = blockIdx.x;
    int n = r >> 3, b = r & 7;
    int c = threadIdx.x;
    float v = in[(size_t)r * CDIM + c];
    float mean = bsum256(v) * (1.f / CDIM);
    float d = v - mean;
    float var = bsum256(d * d) * (1.f / CDIM);
    outp[(size_t)b * (CDIM * NDIM) + (size_t)c * NDIM + n] =
        d * rsqrtf(var + EPSLN) * gamma[c] + beta[c];
}

// ---------------------------------------------------------------------------
// GATv2 aggregation for ONE hypothesis (pointers pre-offset on host).
// Per-warp private partial sums + 8-way tree reduce.
// ---------------------------------------------------------------------------
__global__ __launch_bounds__(256)
void gat_k(const float* __restrict__ base, const float* __restrict__ att,
           const float* __restrict__ gbias, float* __restrict__ outp)
{
    __shared__ float sacc[NHEAD][CDIM];

    int r = blockIdx.x;
    int n = r >> 3, b = r & 7;
    int i = n >> 5, j = n & 31;

    int nbr[5];
    nbr[0] = n;
    nbr[1] = (i > 0)  ? n - 32 : n;
    nbr[2] = (i < 31) ? n + 32 : n;
    nbr[3] = (j > 0)  ? n - 1  : n;
    nbr[4] = (j < 31) ? n + 1  : n;
    bool vld[5] = { true, i > 0, i < 31, j > 0, j < 31 };

    int wid = threadIdx.x >> 5, lane = threadIdx.x & 31;
    const float* xrp  = base + ((size_t)n * BSZ + b) * NLR + HC + wid * CDIM + lane;
    const float* attp = att + wid * CDIM + lane;

    float xrv[8], attv[8];
    #pragma unroll
    for (int t = 0; t < 8; t++) { xrv[t] = xrp[32 * t]; attv[t] = attp[32 * t]; }

    float xlv[5][8], logit[5];
    #pragma unroll
    for (int m = 0; m < 5; m++) {
        const float* xlp = base + ((size_t)nbr[m] * BSZ + b) * NLR + wid * CDIM + lane;
        float s = 0.f;
        #pragma unroll
        for (int t = 0; t < 8; t++) {
            float v = xlp[32 * t];
            xlv[m][t] = v;
            float e = v + xrv[t];
            e = e > 0.f ? e : NEG * e;
            s += e * attv[t];
        }
        #pragma unroll
        for (int o = 16; o > 0; o >>= 1) s += __shfl_xor_sync(0xffffffffu, s, o);
        logit[m] = vld[m] ? s : -1e30f;
    }

    float mx = logit[0];
    #pragma unroll
    for (int m = 1; m < 5; m++) mx = fmaxf(mx, logit[m]);
    float alpha[5], ssum = 0.f;
    #pragma unroll
    for (int m = 0; m < 5; m++) { alpha[m] = expf(logit[m] - mx); ssum += alpha[m]; }
    float scale = 1.f / (ssum * NHEAD);

    #pragma unroll
    for (int t = 0; t < 8; t++) {
        float o = 0.f;
        #pragma unroll
        for (int m = 0; m < 5; m++) o += alpha[m] * xlv[m][t];
        sacc[wid][lane + 32 * t] = o * scale;
    }
    __syncthreads();

    int c = threadIdx.x;
    float s = sacc[0][c];
    #pragma unroll
    for (int w = 1; w < NHEAD; w++) s += sacc[w][c];
    outp[(size_t)b * (CDIM * NDIM) + (size_t)c * NDIM + n] = s + gbias[c];
}

// ---------------------------------------------------------------------------
// Host
// ---------------------------------------------------------------------------
#define STG64_B  ((2 * 64 * GAP + 2 * B_SZE) * 2 * 2)    // total bytes, 2 stages
#define STG128_B ((2 * 128 * GAP + 2 * B_SZE) * 2 * 2)

static void gemm(const uint16_t* Ah, const uint16_t* Al,
                 const uint16_t* Bh, const uint16_t* Bl, int ldb,
                 const float* bias, const float* res,
                 float* C, uint16_t* Chi, uint16_t* Clo,
                 uint16_t* C2hi, uint16_t* C2lo,
                 int M, int N, int K, int act, int Z, int big,
                 size_t zA, size_t zB, size_t zBias, size_t zC, size_t zRes)
{
    if (big) {
        cudaFuncSetAttribute(gemm_k<128>, cudaFuncAttributeMaxDynamicSharedMemorySize, STG128_B);
        gemm_k<128><<<dim3(N / 128, M / 128, Z), 256, STG128_B>>>(
            Ah, Al, Bh, Bl, bias, res, C, Chi, Clo, C2hi, C2lo,
            M, N, K, ldb, act, zA, zB, zBias, zC, zRes);
    } else {
        cudaFuncSetAttribute(gemm_k<64>, cudaFuncAttributeMaxDynamicSharedMemorySize, STG64_B);
        gemm_k<64><<<dim3(N / 128, M / 64, Z), 256, STG64_B>>>(
            Ah, Al, Bh, Bl, bias, res, C, Chi, Clo, C2hi, C2lo,
            M, N, K, ldb, act, zA, zB, zBias, zC, zRes);
    }
}

extern "C" void kernel_launch(void* const* d_in, const int* in_sizes, int n_in,
                              void* d_out, int out_size)
{
    const float* x    = (const float*)d_in[0];
    // d_in[1] = edge_index (int64) — fixed 32x32 grid; computed analytically.
    const float* Wp   = (const float*)d_in[2];
    const float* bp   = (const float*)d_in[3];
    const float* Wm1  = (const float*)d_in[4];
    const float* bm1  = (const float*)d_in[5];
    const float* Wm2  = (const float*)d_in[6];
    const float* bm2  = (const float*)d_in[7];
    const float* Wgca = (const float*)d_in[8];
    const float* bgca = (const float*)d_in[9];
    const float* Wgcc = (const float*)d_in[10];
    const float* bgcc = (const float*)d_in[11];
    const float* Wi1  = (const float*)d_in[12];
    const float* bi1  = (const float*)d_in[13];
    const float* Wi2  = (const float*)d_in[14];
    const float* bi2  = (const float*)d_in[15];
    const float* Wl   = (const float*)d_in[16];
    const float* bl   = (const float*)d_in[17];
    const float* Wr   = (const float*)d_in[18];
    const float* br   = (const float*)d_in[19];
    const float* att  = (const float*)d_in[20];
    const float* gbia = (const float*)d_in[21];
    const float* Wf1  = (const float*)d_in[22];
    const float* bf1  = (const float*)d_in[23];
    const float* Wf2  = (const float*)d_in[24];
    const float* bf2  = (const float*)d_in[25];
    const float* lng  = (const float*)d_in[26];
    const float* lnb  = (const float*)d_in[27];
    float* out = (float*)d_out;

    float *pNode, *pAdj, *pOrig, *pTmp, *pTmp2, *pXlr, *pBlr;
    cudaGetSymbolAddress((void**)&pNode, g_node);
    cudaGetSymbolAddress((void**)&pAdj,  g_adj);
    cudaGetSymbolAddress((void**)&pOrig, g_orig);
    cudaGetSymbolAddress((void**)&pTmp,  g_tmp);
    cudaGetSymbolAddress((void**)&pTmp2, g_tmp2);
    cudaGetSymbolAddress((void**)&pXlr,  g_xlr);
    cudaGetSymbolAddress((void**)&pBlr,  g_blr);

    uint16_t *X0h,*X0l,*Nodeh,*Nodel,*Hidh,*Hidl,*Gateh,*Gatel,*Confh,*Confl;
    uint16_t *Origh,*Origl,*Hid3h,*Hid3l,*Feat3h,*Feat3l;
    cudaGetSymbolAddress((void**)&X0h, bX0h);     cudaGetSymbolAddress((void**)&X0l, bX0l);
    cudaGetSymbolAddress((void**)&Nodeh, bNodeh); cudaGetSymbolAddress((void**)&Nodel, bNodel);
    cudaGetSymbolAddress((void**)&Hidh, bHidh);   cudaGetSymbolAddress((void**)&Hidl, bHidl);
    cudaGetSymbolAddress((void**)&Gateh, bGateh); cudaGetSymbolAddress((void**)&Gatel, bGatel);
    cudaGetSymbolAddress((void**)&Confh, bConfh); cudaGetSymbolAddress((void**)&Confl, bConfl);
    cudaGetSymbolAddress((void**)&Origh, bOrigh); cudaGetSymbolAddress((void**)&Origl, bOrigl);
    cudaGetSymbolAddress((void**)&Hid3h, bHid3h); cudaGetSymbolAddress((void**)&Hid3l, bHid3l);
    cudaGetSymbolAddress((void**)&Feat3h, bFeat3h); cudaGetSymbolAddress((void**)&Feat3l, bFeat3l);

    uint16_t *Wph,*Wpl,*Wm1h,*Wm1l,*Wm2h,*Wm2l,*Gh,*Gl,*Wi1h,*Wi1l,*Wi2h,*Wi2l;
    uint16_t *LRh,*LRl,*Wf1h,*Wf1l,*Wf2h,*Wf2l;
    cudaGetSymbolAddress((void**)&Wph, wWph);   cudaGetSymbolAddress((void**)&Wpl, wWpl);
    cudaGetSymbolAddress((void**)&Wm1h, wWm1h); cudaGetSymbolAddress((void**)&Wm1l, wWm1l);
    cudaGetSymbolAddress((void**)&Wm2h, wWm2h); cudaGetSymbolAddress((void**)&Wm2l, wWm2l);
    cudaGetSymbolAddress((void**)&Gh, wGh);     cudaGetSymbolAddress((void**)&Gl, wGl);
    cudaGetSymbolAddress((void**)&Wi1h, wWi1h); cudaGetSymbolAddress((void**)&Wi1l, wWi1l);
    cudaGetSymbolAddress((void**)&Wi2h, wWi2h); cudaGetSymbolAddress((void**)&Wi2l, wWi2l);
    cudaGetSymbolAddress((void**)&LRh, wLRh);   cudaGetSymbolAddress((void**)&LRl, wLRl);
    cudaGetSymbolAddress((void**)&Wf1h, wWf1h); cudaGetSymbolAddress((void**)&Wf1l, wWf1l);
    cudaGetSymbolAddress((void**)&Wf2h, wWf2h); cudaGetSymbolAddress((void**)&Wf2l, wWf2l);

    const size_t OUTSZ = (size_t)BSZ * CDIM * NDIM;

    // 0. ALL weight conversions in one launch (+ tiny second for Wf1/Wf2)
    ConvJobs jobs;
    int ji = 0;
    auto addjob = [&](const float* s, uint16_t* h, uint16_t* l, int N, int LD, int off, int total) {
        jobs.j[ji++] = ConvJob{ s, h, l, N, LD, off, total / 4 };
    };
    addjob(Wp,   Wph,  Wpl,  CDIM, CDIM, 0, CDIM * CDIM);
    addjob(Wm1,  Wm1h, Wm1l, HIDD, HIDD, 0, CDIM * HIDD);
    addjob(Wm2,  Wm2h, Wm2l, CDIM, CDIM, 0, HIDD * CDIM);
    addjob(Wgcc, Gh,               Gl,               CDIM, CDIM, 0, CDIM * CDIM);
    addjob(Wgca, Gh + CDIM * CDIM, Gl + CDIM * CDIM, CDIM, CDIM, 0, CDIM * CDIM);
    addjob(Wi1,  Wi1h, Wi1l, HIDD, HIDD, 0, NHYP * CDIM * HIDD);
    addjob(Wi2,  Wi2h, Wi2l, CDIM, CDIM, 0, NHYP * HIDD * CDIM);
    for (int z = 0; z < NHYP; z++) {
        size_t ws = (size_t)z * CDIM * HC, wd = (size_t)z * CDIM * NLR;
        addjob(Wl + ws, LRh + wd, LRl + wd, HC, NLR, 0,  CDIM * HC);
        addjob(Wr + ws, LRh + wd, LRl + wd, HC, NLR, HC, CDIM * HC);
    }
    convert_all_k<<<dim3(512, NJOBS), 256>>>(jobs);
    {
        ConvJobs j2{};
        j2.j[0] = ConvJob{ Wf1, Wf1h, Wf1l, FFD,  FFD,  0, CDIM * FFD / 4 };
        j2.j[1] = ConvJob{ Wf2, Wf2h, Wf2l, CDIM, CDIM, 0, FFD * CDIM / 4 };
        for (int t = 2; t < NJOBS; t++) j2.j[t] = ConvJob{ Wf1, Wf1h, Wf1l, FFD, FFD, 0, 0 };
        convert_all_k<<<dim3(128, 2), 256>>>(j2);
    }
    blr_fill_k<<<NHYP, 256>>>(bl, br, pBlr);

    // 1. x -> X0 (bf16 hi/lo)
    transpose_in_k<<<dim3(NDIM / 32, CDIM / 32, BSZ), dim3(32, 32)>>>(x, X0h, X0l);

    // 2. node = X0 @ Wp + bp  (fp32 + bf16)
    gemm(X0h, X0l, Wph, Wpl, CDIM, bp, nullptr,
         pNode, Nodeh, Nodel, nullptr, nullptr, MROWS, CDIM, CDIM, 3, 1, 0, 0,0,0,0,0);

    // 3. hid = relu(node@Wm1+bm1); gate fused into Wm2 epilogue
    gemm(Nodeh, Nodel, Wm1h, Wm1l, HIDD, bm1, nullptr,
         nullptr, Hidh, Hidl, nullptr, nullptr, MROWS, HIDD, CDIM, 1, 1, 0, 0,0,0,0,0);
    gemm(Hidh, Hidl, Wm2h, Wm2l, CDIM, bm2, pNode,
         nullptr, Gateh, Gatel, Gateh + (size_t)MROWS * CDIM, Gatel + (size_t)MROWS * CDIM,
         MROWS, CDIM, HIDD, 2, 1, 0, 0,0,0,0,0);

    // 4. GCN GEMMs batched (z0: xc@Wgcc, z1: xa@Wgca) then the two LN kernels
    gemm(Gateh, Gatel, Gh, Gl, CDIM, nullptr, nullptr,
         pTmp2, nullptr, nullptr, nullptr, nullptr, MROWS, CDIM, CDIM, 0, 2, 0,
         (size_t)MROWS * CDIM, (size_t)CDIM * CDIM, 0, (size_t)MROWS * CDIM, 0);
    gcn_ln_k<<<MROWS, CDIM>>>(pTmp2 + (size_t)MROWS * CDIM, bgca,
                              lng + 0 * CDIM, lnb + 0 * CDIM,
                              pAdj, nullptr, nullptr,
                              nullptr, nullptr, nullptr, nullptr);
    gcn_ln_k<<<MROWS, CDIM>>>(pTmp2, bgcc, lng + 1 * CDIM, lnb + 1 * CDIM,
                              nullptr, Confh, Confl,
                              pAdj, pOrig, Origh, Origl);

    // 5. hypotheses: interv chain z-batched; LR (BM=128) + gat interleaved per
    //    hyp so the single xlr buffer stays L2-hot between producer/consumer
    gemm(Confh, Confl, Wi1h, Wi1l, HIDD, bi1, nullptr,
         nullptr, Hid3h, Hid3l, nullptr, nullptr, MROWS, HIDD, CDIM, 1, NHYP, 0,
         0, (size_t)CDIM * HIDD, HIDD, (size_t)MROWS * HIDD, 0);
    gemm(Hid3h, Hid3l, Wi2h, Wi2l, CDIM, bi2, pOrig,
         nullptr, Feat3h, Feat3l, nullptr, nullptr, MROWS, CDIM, HIDD, 4, NHYP, 0,
         (size_t)MROWS * HIDD, (size_t)HIDD * CDIM, CDIM, (size_t)MROWS * CDIM, 0);
    for (int h = 0; h < NHYP; h++) {
        gemm(Feat3h + (size_t)h * MROWS * CDIM, Feat3l + (size_t)h * MROWS * CDIM,
             LRh + (size_t)h * CDIM * NLR, LRl + (size_t)h * CDIM * NLR, NLR,
             pBlr + (size_t)h * NLR, nullptr,
             pXlr, nullptr, nullptr, nullptr, nullptr, MROWS, NLR, CDIM, 0, 1, 1,
             0, 0, 0, 0, 0);
        gat_k<<<MROWS, 256>>>(pXlr, att + (size_t)h * HC,
                              gbia + (size_t)h * CDIM, out + (size_t)h * OUTSZ);
    }

    // 6. FFN + residual LN -> output slot 3
    gemm(Origh, Origl, Wf1h, Wf1l, FFD, bf1, nullptr,
         nullptr, Hidh, Hidl, nullptr, nullptr, MROWS, FFD, CDIM, 1, 1, 0, 0,0,0,0,0);
    gemm(Hidh, Hidl, Wf2h, Wf2l, CDIM, bf2, pOrig,
         pTmp, nullptr, nullptr, nullptr, nullptr, MROWS, CDIM, FFD, 0, 1, 0, 0,0,0,0,0);
    ln_out_k<<<MROWS, CDIM>>>(pTmp, lng + 2 * CDIM, lnb + 2 * CDIM, out + 3 * OUTSZ);
}

// round 15
// speedup vs baseline: 1.0063x; 1.0063x over previous
#include <cuda_runtime.h>
#include <math.h>
#include <stdint.h>

// Problem constants (fixed by the reference)
#define BSZ   8
#define CDIM  256
#define NDIM  1024          // 32*32
#define MROWS 8192          // NDIM*BSZ
#define NHEAD 8
#define HIDD  128
#define FFD   512
#define NHYP  3
#define HC    2048          // NHEAD*CDIM
#define NLR   4096          // fused Wl|Wr output width
#define NEG   0.2f
#define EPSLN 1e-5f

// ---------------------------------------------------------------------------
// Static scratch (no allocations allowed)
// ---------------------------------------------------------------------------
__device__ float g_node[MROWS * CDIM];
__device__ float g_adj [MROWS * CDIM];
__device__ float g_orig[MROWS * CDIM];
__device__ float g_tmp [MROWS * CDIM];
__device__ float g_tmp2[2 * MROWS * CDIM];     // GCN GEMM outs: z0=conf, z1=adj
__device__ float g_xlr [(size_t)MROWS * NLR];  // SINGLE hyp buffer, reused (L2-hot)
__device__ float g_blr [NHYP * NLR];

// bf16 (bit-pattern uint16) hi/lo activation buffers (row-major [M][K])
__device__ uint16_t bX0h [MROWS * CDIM], bX0l [MROWS * CDIM];
__device__ uint16_t bNodeh[MROWS * CDIM], bNodel[MROWS * CDIM];
__device__ uint16_t bHidh[MROWS * FFD],  bHidl[MROWS * FFD];
__device__ uint16_t bGateh[2 * MROWS * CDIM], bGatel[2 * MROWS * CDIM]; // z0=xc, z1=xa
__device__ uint16_t bConfh[MROWS * CDIM], bConfl[MROWS * CDIM];
__device__ uint16_t bOrigh[MROWS * CDIM], bOrigl[MROWS * CDIM];
__device__ uint16_t bHid3h[NHYP * MROWS * HIDD], bHid3l[NHYP * MROWS * HIDD];
__device__ uint16_t bFeat3h[NHYP * MROWS * CDIM], bFeat3l[NHYP * MROWS * CDIM];

// weight hi/lo buffers, stored [K][N] N-major (GEMM B operand)
__device__ uint16_t wWph [CDIM*CDIM],  wWpl [CDIM*CDIM];
__device__ uint16_t wWm1h[CDIM*HIDD],  wWm1l[CDIM*HIDD];
__device__ uint16_t wWm2h[HIDD*CDIM],  wWm2l[HIDD*CDIM];
__device__ uint16_t wGh  [2*CDIM*CDIM], wGl [2*CDIM*CDIM];      // z0=Wgcc, z1=Wgca
__device__ uint16_t wWi1h[NHYP*CDIM*HIDD], wWi1l[NHYP*CDIM*HIDD];
__device__ uint16_t wWi2h[NHYP*HIDD*CDIM], wWi2l[NHYP*HIDD*CDIM];
__device__ uint16_t wLRh [NHYP*(size_t)CDIM*NLR], wLRl[NHYP*(size_t)CDIM*NLR];
__device__ uint16_t wWf1h[CDIM*FFD],   wWf1l[CDIM*FFD];
__device__ uint16_t wWf2h[FFD*CDIM],   wWf2l[FFD*CDIM];

// ---------------------------------------------------------------------------
// bf16 split helpers
// ---------------------------------------------------------------------------
__device__ __forceinline__ uint32_t bf16_rn(float f)
{
    uint32_t u = __float_as_uint(f);
    return (u + 0x7FFFu + ((u >> 16) & 1u)) >> 16;
}
__device__ __forceinline__ void bf16_split(float f, uint32_t& h, uint32_t& l)
{
    h = bf16_rn(f);
    float rem = f - __uint_as_float(h << 16);
    l = bf16_rn(rem);
}
__device__ __forceinline__ void store_pair(uint16_t* hi, uint16_t* lo, size_t o,
                                           float v0, float v1)
{
    uint32_t h0, l0, h1, l1;
    bf16_split(v0, h0, l0);
    bf16_split(v1, h1, l1);
    *(uint32_t*)&hi[o] = h0 | (h1 << 16);
    *(uint32_t*)&lo[o] = l0 | (l1 << 16);
}

// ---------------------------------------------------------------------------
// ALL weight conversions in ONE launch (job table by value, blockIdx.y = job)
// ---------------------------------------------------------------------------
#define NJOBS 13
struct ConvJob {
    const float* src;
    uint16_t *hi, *lo;
    int N, LD, off, n4;
};
struct ConvJobs { ConvJob j[NJOBS]; };

__global__ void convert_all_k(ConvJobs jobs)
{
    ConvJob jb = jobs.j[blockIdx.y];
    int i = blockIdx.x * blockDim.x + threadIdx.x;
    if (i >= jb.n4) return;
    int e = i * 4;
    int k = e / jb.N, n = e - k * jb.N;
    float4 q = *(const float4*)(jb.src + e);
    uint32_t h0,h1,h2,h3,l0,l1,l2,l3;
    bf16_split(q.x,h0,l0); bf16_split(q.y,h1,l1);
    bf16_split(q.z,h2,l2); bf16_split(q.w,h3,l3);
    size_t d = (size_t)k * jb.LD + jb.off + n;
    *(uint2*)(jb.hi + d) = make_uint2(h0 | (h1 << 16), h2 | (h3 << 16));
    *(uint2*)(jb.lo + d) = make_uint2(l0 | (l1 << 16), l2 | (l3 << 16));
}

// blr[z][0:HC)=bl[z], blr[z][HC:NLR)=br[z]
__global__ void blr_fill_k(const float* __restrict__ bl, const float* __restrict__ br,
                           float* __restrict__ blr)
{
    int z = blockIdx.x;
    for (int c = threadIdx.x; c < NLR; c += blockDim.x)
        blr[(size_t)z * NLR + c] = (c < HC) ? bl[(size_t)z * HC + c]
                                            : br[(size_t)z * HC + c - HC];
}

// ---------------------------------------------------------------------------
// Transpose: x[B,C,N] -> X0[(n*B+b), C] as bf16 hi/lo
// ---------------------------------------------------------------------------
__global__ void transpose_in_k(const float* __restrict__ x,
                               uint16_t* __restrict__ X0h, uint16_t* __restrict__ X0l)
{
    __shared__ float s[32][33];
    int b  = blockIdx.z;
    int c0 = blockIdx.y * 32;
    int n0 = blockIdx.x * 32;
    int tx = threadIdx.x, ty = threadIdx.y;
    s[ty][tx] = x[((size_t)b * CDIM + (c0 + ty)) * NDIM + n0 + tx];
    __syncthreads();
    float v = s[tx][ty];
    uint32_t h, l;
    bf16_split(v, h, l);
    size_t o = ((size_t)(n0 + ty) * BSZ + b) * CDIM + c0 + tx;
    X0h[o] = (uint16_t)h;
    X0l[o] = (uint16_t)l;
}

// ---------------------------------------------------------------------------
// mma.sync tensor-core GEMM, templated BM (64 default; 32 for small-grid
// GEMMs to fill the chip). BN=128, BK=32, 2-stage cp.async, z-batched.
// 3-term split: AhBh + AhBl + AlBh, fp32 accumulate.
// act: 0 fp32(+res), 1 relu->bf16, 2 gate->(C=sig*res, C2=(1-sig)*res),
//      3 fp32+bf16, 4 (bias+res)->bf16
// ---------------------------------------------------------------------------
__device__ __forceinline__ uint32_t sptr(const void* p)
{
    return (uint32_t)__cvta_generic_to_shared(p);
}
__device__ __forceinline__ void cp16_s(uint32_t dst, const void* src)
{
    asm volatile("cp.async.cg.shared.global [%0], [%1], 16;" :: "r"(dst), "l"(src));
}
__device__ __forceinline__ void ldsm4(uint32_t* r, uint32_t addr)
{
    asm volatile("ldmatrix.sync.aligned.m8n8.x4.shared.b16 {%0,%1,%2,%3}, [%4];"
                 : "=r"(r[0]), "=r"(r[1]), "=r"(r[2]), "=r"(r[3]) : "r"(addr));
}
__device__ __forceinline__ void ldsm4t(uint32_t* r, uint32_t addr)
{
    asm volatile("ldmatrix.sync.aligned.m8n8.x4.trans.shared.b16 {%0,%1,%2,%3}, [%4];"
                 : "=r"(r[0]), "=r"(r[1]), "=r"(r[2]), "=r"(r[3]) : "r"(addr));
}
__device__ __forceinline__ void mma16816(float* c, const uint32_t* a, uint32_t b0, uint32_t b1)
{
    asm volatile(
        "mma.sync.aligned.m16n8k16.row.col.f32.bf16.bf16.f32 "
        "{%0,%1,%2,%3}, {%4,%5,%6,%7}, {%8,%9}, {%0,%1,%2,%3};"
        : "+f"(c[0]), "+f"(c[1]), "+f"(c[2]), "+f"(c[3])
        : "r"(a[0]), "r"(a[1]), "r"(a[2]), "r"(a[3]), "r"(b0), "r"(b1));
}

#define GAP  40                       // A smem pitch (elems): 80B rows, conflict-free
#define GBP  136                      // B smem pitch (elems): 272B rows, conflict-free
#define B_SZE (32 * GBP)              // 4352 elems per B array per stage

template<int BM>
__global__ __launch_bounds__(256, 3)
void gemm_k(const uint16_t* __restrict__ Ah, const uint16_t* __restrict__ Al,
            const uint16_t* __restrict__ Bh, const uint16_t* __restrict__ Bl,
            const float* __restrict__ bias, const float* __restrict__ res,
            float* __restrict__ C,
            uint16_t* __restrict__ Chi, uint16_t* __restrict__ Clo,
            uint16_t* __restrict__ C2hi, uint16_t* __restrict__ C2lo,
            int M, int N, int K, int ldb, int act,
            size_t zA, size_t zB, size_t zBias, size_t zC, size_t zRes)
{
    constexpr int WARPS_M = BM / 32;          // 1 or 2
    constexpr int WARPS_N = 8 / WARPS_M;      // 8 or 4
    constexpr int WN  = 128 / WARPS_N;        // 16 or 32
    constexpr int NF  = WN / 8;               // 2 or 4
    constexpr int NB  = WN / 16;              // 1 or 2
    constexpr int ASZ = BM * GAP;
    constexpr int STG = 2 * ASZ + 2 * B_SZE;  // stage elems
    constexpr int ACH = BM * 4;               // 16B chunks per A array
    constexpr int AV  = (ACH + 255) / 256;

    extern __shared__ __align__(16) uint16_t sm[];
    int z = blockIdx.z;
    Ah += z * zA; Al += z * zA;
    Bh += z * zB; Bl += z * zB;
    if (bias) bias += z * zBias;
    if (res)  res  += z * zRes;
    if (C)    C    += z * zC;
    if (Chi)  { Chi  += z * zC; Clo  += z * zC; }
    if (C2hi) { C2hi += z * zC; C2lo += z * zC; }

    int tid = threadIdx.x, wid = tid >> 5, lane = tid & 31;
    int wm = wid % WARPS_M, wn = wid / WARPS_M;
    int m0 = blockIdx.y * BM, n0 = blockIdx.x * 128;

    float acc[2][NF][4] = {};

    int a_row  = wm * 32 + (lane & 15);
    int a_koff = (lane >> 4) * 8;
    int b_k    = (lane & 7) + (lane & 8);
    int b_n    = wn * WN + ((lane & 16) >> 1);

    uint32_t smb = sptr(sm);

    auto load_stage = [&](int kt, int st) {
        uint32_t base = smb + st * (STG * 2);
        int kg = kt * 32;
        #pragma unroll
        for (int v = 0; v < AV; v++) {
            int idx = tid + v * 256;
            if (ACH >= 256 || idx < ACH) {
                int row = idx >> 2, kc = (idx & 3) * 8;
                size_t ga = (size_t)(m0 + row) * K + kg + kc;
                uint32_t da = base + (row * GAP + kc) * 2;
                cp16_s(da,           Ah + ga);
                cp16_s(da + ASZ * 2, Al + ga);
            }
        }
        #pragma unroll
        for (int v = 0; v < 2; v++) {
            int idx = tid + v * 256;
            int brow = idx >> 4, bnc = (idx & 15) * 8;
            size_t gb = (size_t)(kg + brow) * ldb + n0 + bnc;
            uint32_t db = base + 2 * ASZ * 2 + (brow * GBP + bnc) * 2;
            cp16_s(db,             Bh + gb);
            cp16_s(db + B_SZE * 2, Bl + gb);
        }
    };

    int KT = K / 32;
    load_stage(0, 0);
    asm volatile("cp.async.commit_group;");

    int buf = 0;
    for (int kt = 0; kt < KT; kt++) {
        if (kt + 1 < KT) {
            load_stage(kt + 1, buf ^ 1);
            asm volatile("cp.async.commit_group;");
            asm volatile("cp.async.wait_group 1;");
        } else {
            asm volatile("cp.async.wait_group 0;");
        }
        __syncthreads();

        uint32_t pAh = smb + buf * (STG * 2);
        uint32_t pAl = pAh + ASZ * 2;
        uint32_t pBh = pAh + 2 * ASZ * 2;
        uint32_t pBl = pBh + B_SZE * 2;

        #pragma unroll
        for (int ks = 0; ks < 2; ks++) {
            uint32_t ah[2][4], al[2][4];
            #pragma unroll
            for (int mf = 0; mf < 2; mf++) {
                uint32_t off = ((a_row + mf * 16) * GAP + ks * 16 + a_koff) * 2;
                ldsm4(ah[mf], pAh + off);
                ldsm4(al[mf], pAl + off);
            }
            #pragma unroll
            for (int nb = 0; nb < NB; nb++) {
                uint32_t bh[4], bl[4];
                uint32_t boff = ((ks * 16 + b_k) * GBP + b_n + nb * 16) * 2;
                ldsm4t(bh, pBh + boff);
                ldsm4t(bl, pBl + boff);
                #pragma unroll
                for (int mf = 0; mf < 2; mf++) {
                    mma16816(acc[mf][2*nb],   ah[mf], bh[0], bh[1]);
                    mma16816(acc[mf][2*nb],   ah[mf], bl[0], bl[1]);
                    mma16816(acc[mf][2*nb],   al[mf], bh[0], bh[1]);
                    mma16816(acc[mf][2*nb+1], ah[mf], bh[2], bh[3]);
                    mma16816(acc[mf][2*nb+1], ah[mf], bl[2], bl[3]);
                    mma16816(acc[mf][2*nb+1], al[mf], bh[2], bh[3]);
                }
            }
        }
        __syncthreads();
        buf ^= 1;
    }

    // ---- epilogue
    int gr = lane >> 2, gc = (lane & 3) * 2;
    #pragma unroll
    for (int mf = 0; mf < 2; mf++) {
        #pragma unroll
        for (int nf = 0; nf < NF; nf++) {
            int n = n0 + wn * WN + nf * 8 + gc;
            #pragma unroll
            for (int half = 0; half < 2; half++) {
                int m = m0 + wm * 32 + mf * 16 + gr + half * 8;
                size_t o = (size_t)m * N + n;
                float v0 = acc[mf][nf][2*half + 0];
                float v1 = acc[mf][nf][2*half + 1];
                if (bias) { v0 += __ldg(&bias[n]); v1 += __ldg(&bias[n + 1]); }
                if (act == 0) {
                    if (res) { float2 rr = *(const float2*)&res[o]; v0 += rr.x; v1 += rr.y; }
                    *(float2*)&C[o] = make_float2(v0, v1);
                } else if (act == 1) {
                    store_pair(Chi, Clo, o, fmaxf(v0, 0.f), fmaxf(v1, 0.f));
                } else if (act == 2) {
                    float2 nd = *(const float2*)&res[o];
                    float s0 = 1.f / (1.f + expf(-v0));
                    float s1 = 1.f / (1.f + expf(-v1));
                    store_pair(Chi,  Clo,  o, s0 * nd.x, s1 * nd.y);
                    store_pair(C2hi, C2lo, o, (1.f - s0) * nd.x, (1.f - s1) * nd.y);
                } else if (act == 3) {
                    *(float2*)&C[o] = make_float2(v0, v1);
                    store_pair(Chi, Clo, o, v0, v1);
                } else { // act == 4
                    float2 rr = *(const float2*)&res[o];
                    store_pair(Chi, Clo, o, v0 + rr.x, v1 + rr.y);
                }
            }
        }
    }
}

// ---------------------------------------------------------------------------
// Block-wide sum over 256 threads
// ---------------------------------------------------------------------------
__device__ __forceinline__ float bsum256(float v)
{
    __shared__ float s[256];
    int t = threadIdx.x;
    s[t] = v; __syncthreads();
    #pragma unroll
    for (int o = 128; o > 0; o >>= 1) {
        if (t < o) s[t] += s[t + o];
        __syncthreads();
    }
    float r = s[0];
    __syncthreads();
    return r;
}

__device__ __forceinline__ float grid_deg(int i, int j)
{
    return 1.f + (i > 0) + (i < 31) + (j > 0) + (j < 31);
}

// ---------------------------------------------------------------------------
// Fused GCN aggregation + bias + LayerNorm.
// ---------------------------------------------------------------------------
__global__ __launch_bounds__(256)
void gcn_ln_k(const float* __restrict__ hw, const float* __restrict__ bg,
              const float* __restrict__ gamma, const float* __restrict__ beta,
              float* __restrict__ out_f32,
              uint16_t* __restrict__ out_hi, uint16_t* __restrict__ out_lo,
              const float* __restrict__ addin, float* __restrict__ out2_f32,
              uint16_t* __restrict__ out2_hi, uint16_t* __restrict__ out2_lo)
{
    int r = blockIdx.x;
    int n = r >> 3, b = r & 7;
    int i = n >> 5, j = n & 31;
    float degn = grid_deg(i, j);

    int   nbr[5];
    float nrm[5];
    nbr[0] = n;                       nrm[0] = 1.f / degn;
    nbr[1] = (i > 0)  ? n - 32 : n;
    nbr[2] = (i < 31) ? n + 32 : n;
    nbr[3] = (j > 0)  ? n - 1  : n;
    nbr[4] = (j < 31) ? n + 1  : n;
    bool vld[5] = { true, i > 0, i < 31, j > 0, j < 31 };
    #pragma unroll
    for (int t = 1; t < 5; t++) {
        int m = nbr[t];
        float degm = grid_deg(m >> 5, m & 31);
        nrm[t] = vld[t] ? rsqrtf(degm * degn) : 0.f;
    }

    int c = threadIdx.x;
    float acc = bg[c];
    #pragma unroll
    for (int t = 0; t < 5; t++)
        acc += nrm[t] * hw[((size_t)nbr[t] * BSZ + b) * CDIM + c];

    float mean = bsum256(acc) * (1.f / CDIM);
    float d = acc - mean;
    float var = bsum256(d * d) * (1.f / CDIM);
    float o = d * rsqrtf(var + EPSLN) * gamma[c] + beta[c];
    size_t idx = (size_t)r * CDIM + c;

    if (out_f32) out_f32[idx] = o;
    if (out_hi) {
        uint32_t h, l; bf16_split(o, h, l);
        out_hi[idx] = (uint16_t)h; out_lo[idx] = (uint16_t)l;
    }
    if (addin) {
        float o2 = o + addin[idx];
        out2_f32[idx] = o2;
        uint32_t h, l; bf16_split(o2, h, l);
        out2_hi[idx] = (uint16_t)h; out2_lo[idx] = (uint16_t)l;
    }
}

// ---------------------------------------------------------------------------
// Final residual LayerNorm, writing image layout out[b,c,n]
// ---------------------------------------------------------------------------
__global__ __launch_bounds__(256)
void ln_out_k(const float* __restrict__ in, const float* __restrict__ gamma,
              const float* __restrict__ beta, float* __restrict__ outp)
{
    int r = blockIdx.x;
    int n = r >> 3, b = r & 7;
    int c = threadIdx.x;
    float v = in[(size_t)r * CDIM + c];
    float mean = bsum256(v) * (1.f / CDIM);
    float d = v - mean;
    float var = bsum256(d * d) * (1.f / CDIM);
    outp[(size_t)b * (CDIM * NDIM) + (size_t)c * NDIM + n] =
        d * rsqrtf(var + EPSLN) * gamma[c] + beta[c];
}

// ---------------------------------------------------------------------------
// GATv2 aggregation for ONE hypothesis (pointers pre-offset on host).
// Per-warp private partial sums + 8-way tree reduce.
// ---------------------------------------------------------------------------
__global__ __launch_bounds__(256)
void gat_k(const float* __restrict__ base, const float* __restrict__ att,
           const float* __restrict__ gbias, float* __restrict__ outp)
{
    __shared__ float sacc[NHEAD][CDIM];

    int r = blockIdx.x;
    int n = r >> 3, b = r & 7;
    int i = n >> 5, j = n & 31;

    int nbr[5];
    nbr[0] = n;
    nbr[1] = (i > 0)  ? n - 32 : n;
    nbr[2] = (i < 31) ? n + 32 : n;
    nbr[3] = (j > 0)  ? n - 1  : n;
    nbr[4] = (j < 31) ? n + 1  : n;
    bool vld[5] = { true, i > 0, i < 31, j > 0, j < 31 };

    int wid = threadIdx.x >> 5, lane = threadIdx.x & 31;
    const float* xrp  = base + ((size_t)n * BSZ + b) * NLR + HC + wid * CDIM + lane;
    const float* attp = att + wid * CDIM + lane;

    float xrv[8], attv[8];
    #pragma unroll
    for (int t = 0; t < 8; t++) { xrv[t] = xrp[32 * t]; attv[t] = attp[32 * t]; }

    float xlv[5][8], logit[5];
    #pragma unroll
    for (int m = 0; m < 5; m++) {
        const float* xlp = base + ((size_t)nbr[m] * BSZ + b) * NLR + wid * CDIM + lane;
        float s = 0.f;
        #pragma unroll
        for (int t = 0; t < 8; t++) {
            float v = xlp[32 * t];
            xlv[m][t] = v;
            float e = v + xrv[t];
            e = e > 0.f ? e : NEG * e;
            s += e * attv[t];
        }
        #pragma unroll
        for (int o = 16; o > 0; o >>= 1) s += __shfl_xor_sync(0xffffffffu, s, o);
        logit[m] = vld[m] ? s : -1e30f;
    }

    float mx = logit[0];
    #pragma unroll
    for (int m = 1; m < 5; m++) mx = fmaxf(mx, logit[m]);
    float alpha[5], ssum = 0.f;
    #pragma unroll
    for (int m = 0; m < 5; m++) { alpha[m] = expf(logit[m] - mx); ssum += alpha[m]; }
    float scale = 1.f / (ssum * NHEAD);

    #pragma unroll
    for (int t = 0; t < 8; t++) {
        float o = 0.f;
        #pragma unroll
        for (int m = 0; m < 5; m++) o += alpha[m] * xlv[m][t];
        sacc[wid][lane + 32 * t] = o * scale;
    }
    __syncthreads();

    int c = threadIdx.x;
    float s = sacc[0][c];
    #pragma unroll
    for (int w = 1; w < NHEAD; w++) s += sacc[w][c];
    outp[(size_t)b * (CDIM * NDIM) + (size_t)c * NDIM + n] = s + gbias[c];
}

// ---------------------------------------------------------------------------
// Host
// ---------------------------------------------------------------------------
#define STG64_B ((2 * 64 * GAP + 2 * B_SZE) * 2 * 2)    // total bytes, 2 stages
#define STG32_B ((2 * 32 * GAP + 2 * B_SZE) * 2 * 2)

static void gemm(const uint16_t* Ah, const uint16_t* Al,
                 const uint16_t* Bh, const uint16_t* Bl, int ldb,
                 const float* bias, const float* res,
                 float* C, uint16_t* Chi, uint16_t* Clo,
                 uint16_t* C2hi, uint16_t* C2lo,
                 int M, int N, int K, int act, int Z,
                 size_t zA, size_t zB, size_t zBias, size_t zC, size_t zRes)
{
    long blocks64 = (long)(M / 64) * (N / 128) * Z;
    if (blocks64 < 400) {
        // small grid: BM=32 doubles fill on the 444-slot chip
        cudaFuncSetAttribute(gemm_k<32>, cudaFuncAttributeMaxDynamicSharedMemorySize, STG32_B);
        gemm_k<32><<<dim3(N / 128, M / 32, Z), 256, STG32_B>>>(
            Ah, Al, Bh, Bl, bias, res, C, Chi, Clo, C2hi, C2lo,
            M, N, K, ldb, act, zA, zB, zBias, zC, zRes);
    } else {
        cudaFuncSetAttribute(gemm_k<64>, cudaFuncAttributeMaxDynamicSharedMemorySize, STG64_B);
        gemm_k<64><<<dim3(N / 128, M / 64, Z), 256, STG64_B>>>(
            Ah, Al, Bh, Bl, bias, res, C, Chi, Clo, C2hi, C2lo,
            M, N, K, ldb, act, zA, zB, zBias, zC, zRes);
    }
}

extern "C" void kernel_launch(void* const* d_in, const int* in_sizes, int n_in,
                              void* d_out, int out_size)
{
    const float* x    = (const float*)d_in[0];
    // d_in[1] = edge_index (int64) — fixed 32x32 grid; computed analytically.
    const float* Wp   = (const float*)d_in[2];
    const float* bp   = (const float*)d_in[3];
    const float* Wm1  = (const float*)d_in[4];
    const float* bm1  = (const float*)d_in[5];
    const float* Wm2  = (const float*)d_in[6];
    const float* bm2  = (const float*)d_in[7];
    const float* Wgca = (const float*)d_in[8];
    const float* bgca = (const float*)d_in[9];
    const float* Wgcc = (const float*)d_in[10];
    const float* bgcc = (const float*)d_in[11];
    const float* Wi1  = (const float*)d_in[12];
    const float* bi1  = (const float*)d_in[13];
    const float* Wi2  = (const float*)d_in[14];
    const float* bi2  = (const float*)d_in[15];
    const float* Wl   = (const float*)d_in[16];
    const float* bl   = (const float*)d_in[17];
    const float* Wr   = (const float*)d_in[18];
    const float* br   = (const float*)d_in[19];
    const float* att  = (const float*)d_in[20];
    const float* gbia = (const float*)d_in[21];
    const float* Wf1  = (const float*)d_in[22];
    const float* bf1  = (const float*)d_in[23];
    const float* Wf2  = (const float*)d_in[24];
    const float* bf2  = (const float*)d_in[25];
    const float* lng  = (const float*)d_in[26];
    const float* lnb  = (const float*)d_in[27];
    float* out = (float*)d_out;

    float *pNode, *pAdj, *pOrig, *pTmp, *pTmp2, *pXlr, *pBlr;
    cudaGetSymbolAddress((void**)&pNode, g_node);
    cudaGetSymbolAddress((void**)&pAdj,  g_adj);
    cudaGetSymbolAddress((void**)&pOrig, g_orig);
    cudaGetSymbolAddress((void**)&pTmp,  g_tmp);
    cudaGetSymbolAddress((void**)&pTmp2, g_tmp2);
    cudaGetSymbolAddress((void**)&pXlr,  g_xlr);
    cudaGetSymbolAddress((void**)&pBlr,  g_blr);

    uint16_t *X0h,*X0l,*Nodeh,*Nodel,*Hidh,*Hidl,*Gateh,*Gatel,*Confh,*Confl;
    uint16_t *Origh,*Origl,*Hid3h,*Hid3l,*Feat3h,*Feat3l;
    cudaGetSymbolAddress((void**)&X0h, bX0h);     cudaGetSymbolAddress((void**)&X0l, bX0l);
    cudaGetSymbolAddress((void**)&Nodeh, bNodeh); cudaGetSymbolAddress((void**)&Nodel, bNodel);
    cudaGetSymbolAddress((void**)&Hidh, bHidh);   cudaGetSymbolAddress((void**)&Hidl, bHidl);
    cudaGetSymbolAddress((void**)&Gateh, bGateh); cudaGetSymbolAddress((void**)&Gatel, bGatel);
    cudaGetSymbolAddress((void**)&Confh, bConfh); cudaGetSymbolAddress((void**)&Confl, bConfl);
    cudaGetSymbolAddress((void**)&Origh, bOrigh); cudaGetSymbolAddress((void**)&Origl, bOrigl);
    cudaGetSymbolAddress((void**)&Hid3h, bHid3h); cudaGetSymbolAddress((void**)&Hid3l, bHid3l);
    cudaGetSymbolAddress((void**)&Feat3h, bFeat3h); cudaGetSymbolAddress((void**)&Feat3l, bFeat3l);

    uint16_t *Wph,*Wpl,*Wm1h,*Wm1l,*Wm2h,*Wm2l,*Gh,*Gl,*Wi1h,*Wi1l,*Wi2h,*Wi2l;
    uint16_t *LRh,*LRl,*Wf1h,*Wf1l,*Wf2h,*Wf2l;
    cudaGetSymbolAddress((void**)&Wph, wWph);   cudaGetSymbolAddress((void**)&Wpl, wWpl);
    cudaGetSymbolAddress((void**)&Wm1h, wWm1h); cudaGetSymbolAddress((void**)&Wm1l, wWm1l);
    cudaGetSymbolAddress((void**)&Wm2h, wWm2h); cudaGetSymbolAddress((void**)&Wm2l, wWm2l);
    cudaGetSymbolAddress((void**)&Gh, wGh);     cudaGetSymbolAddress((void**)&Gl, wGl);
    cudaGetSymbolAddress((void**)&Wi1h, wWi1h); cudaGetSymbolAddress((void**)&Wi1l, wWi1l);
    cudaGetSymbolAddress((void**)&Wi2h, wWi2h); cudaGetSymbolAddress((void**)&Wi2l, wWi2l);
    cudaGetSymbolAddress((void**)&LRh, wLRh);   cudaGetSymbolAddress((void**)&LRl, wLRl);
    cudaGetSymbolAddress((void**)&Wf1h, wWf1h); cudaGetSymbolAddress((void**)&Wf1l, wWf1l);
    cudaGetSymbolAddress((void**)&Wf2h, wWf2h); cudaGetSymbolAddress((void**)&Wf2l, wWf2l);

    const size_t OUTSZ = (size_t)BSZ * CDIM * NDIM;

    // 0. ALL weight conversions in one launch (+ tiny second for Wf1/Wf2)
    ConvJobs jobs;
    int ji = 0;
    auto addjob = [&](const float* s, uint16_t* h, uint16_t* l, int N, int LD, int off, int total) {
        jobs.j[ji++] = ConvJob{ s, h, l, N, LD, off, total / 4 };
    };
    addjob(Wp,   Wph,  Wpl,  CDIM, CDIM, 0, CDIM * CDIM);
    addjob(Wm1,  Wm1h, Wm1l, HIDD, HIDD, 0, CDIM * HIDD);
    addjob(Wm2,  Wm2h, Wm2l, CDIM, CDIM, 0, HIDD * CDIM);
    addjob(Wgcc, Gh,               Gl,               CDIM, CDIM, 0, CDIM * CDIM);
    addjob(Wgca, Gh + CDIM * CDIM, Gl + CDIM * CDIM, CDIM, CDIM, 0, CDIM * CDIM);
    addjob(Wi1,  Wi1h, Wi1l, HIDD, HIDD, 0, NHYP * CDIM * HIDD);
    addjob(Wi2,  Wi2h, Wi2l, CDIM, CDIM, 0, NHYP * HIDD * CDIM);
    for (int z = 0; z < NHYP; z++) {
        size_t ws = (size_t)z * CDIM * HC, wd = (size_t)z * CDIM * NLR;
        addjob(Wl + ws, LRh + wd, LRl + wd, HC, NLR, 0,  CDIM * HC);
        addjob(Wr + ws, LRh + wd, LRl + wd, HC, NLR, HC, CDIM * HC);
    }
    convert_all_k<<<dim3(512, NJOBS), 256>>>(jobs);
    {
        ConvJobs j2{};
        j2.j[0] = ConvJob{ Wf1, Wf1h, Wf1l, FFD,  FFD,  0, CDIM * FFD / 4 };
        j2.j[1] = ConvJob{ Wf2, Wf2h, Wf2l, CDIM, CDIM, 0, FFD * CDIM / 4 };
        for (int t = 2; t < NJOBS; t++) j2.j[t] = ConvJob{ Wf1, Wf1h, Wf1l, FFD, FFD, 0, 0 };
        convert_all_k<<<dim3(128, 2), 256>>>(j2);
    }
    blr_fill_k<<<NHYP, 256>>>(bl, br, pBlr);

    // 1. x -> X0 (bf16 hi/lo)
    transpose_in_k<<<dim3(NDIM / 32, CDIM / 32, BSZ), dim3(32, 32)>>>(x, X0h, X0l);

    // 2. node = X0 @ Wp + bp  (fp32 + bf16)   [256 -> 512 blocks via BM=32]
    gemm(X0h, X0l, Wph, Wpl, CDIM, bp, nullptr,
         pNode, Nodeh, Nodel, nullptr, nullptr, MROWS, CDIM, CDIM, 3, 1, 0,0,0,0,0);

    // 3. hid = relu(node@Wm1+bm1); gate fused into Wm2 epilogue
    gemm(Nodeh, Nodel, Wm1h, Wm1l, HIDD, bm1, nullptr,
         nullptr, Hidh, Hidl, nullptr, nullptr, MROWS, HIDD, CDIM, 1, 1, 0,0,0,0,0);
    gemm(Hidh, Hidl, Wm2h, Wm2l, CDIM, bm2, pNode,
         nullptr, Gateh, Gatel, Gateh + (size_t)MROWS * CDIM, Gatel + (size_t)MROWS * CDIM,
         MROWS, CDIM, HIDD, 2, 1, 0,0,0,0,0);

    // 4. GCN GEMMs batched (z0: xc@Wgcc, z1: xa@Wgca) then the two LN kernels
    gemm(Gateh, Gatel, Gh, Gl, CDIM, nullptr, nullptr,
         pTmp2, nullptr, nullptr, nullptr, nullptr, MROWS, CDIM, CDIM, 0, 2,
         (size_t)MROWS * CDIM, (size_t)CDIM * CDIM, 0, (size_t)MROWS * CDIM, 0);
    gcn_ln_k<<<MROWS, CDIM>>>(pTmp2 + (size_t)MROWS * CDIM, bgca,
                              lng + 0 * CDIM, lnb + 0 * CDIM,
                              pAdj, nullptr, nullptr,
                              nullptr, nullptr, nullptr, nullptr);
    gcn_ln_k<<<MROWS, CDIM>>>(pTmp2, bgcc, lng + 1 * CDIM, lnb + 1 * CDIM,
                              nullptr, Confh, Confl,
                              pAdj, pOrig, Origh, Origl);

    // 5. hypotheses: interv chain z-batched; LR (BM=64) + gat interleaved per
    //    hyp so the single xlr buffer stays L2-hot between producer/consumer
    gemm(Confh, Confl, Wi1h, Wi1l, HIDD, bi1, nullptr,
         nullptr, Hid3h, Hid3l, nullptr, nullptr, MROWS, HIDD, CDIM, 1, NHYP,
         0, (size_t)CDIM * HIDD, HIDD, (size_t)MROWS * HIDD, 0);
    gemm(Hid3h, Hid3l, Wi2h, Wi2l, CDIM, bi2, pOrig,
         nullptr, Feat3h, Feat3l, nullptr, nullptr, MROWS, CDIM, HIDD, 4, NHYP,
         (size_t)MROWS * HIDD, (size_t)HIDD * CDIM, CDIM, (size_t)MROWS * CDIM, 0);
    for (int h = 0; h < NHYP; h++) {
        gemm(Feat3h + (size_t)h * MROWS * CDIM, Feat3l + (size_t)h * MROWS * CDIM,
             LRh + (size_t)h * CDIM * NLR, LRl + (size_t)h * CDIM * NLR, NLR,
             pBlr + (size_t)h * NLR, nullptr,
             pXlr, nullptr, nullptr, nullptr, nullptr, MROWS, NLR, CDIM, 0, 1,
             0, 0, 0, 0, 0);
        gat_k<<<MROWS, 256>>>(pXlr, att + (size_t)h * HC,
                              gbia + (size_t)h * CDIM, out + (size_t)h * OUTSZ);
    }

    // 6. FFN + residual LN -> output slot 3
    gemm(Origh, Origl, Wf1h, Wf1l, FFD, bf1, nullptr,
         nullptr, Hidh, Hidl, nullptr, nullptr, MROWS, FFD, CDIM, 1, 1, 0,0,0,0,0);
    gemm(Hidh, Hidl, Wf2h, Wf2l, CDIM, bf2, pOrig,
         pTmp, nullptr, nullptr, nullptr, nullptr, MROWS, CDIM, FFD, 0, 1, 0,0,0,0,0);
    ln_out_k<<<MROWS, CDIM>>>(pTmp, lng + 2 * CDIM, lnb + 2 * CDIM, out + 3 * OUTSZ);
}

// round 16
// speedup vs baseline: 1.0264x; 1.0200x over previous
#include <cuda_runtime.h>
#include <math.h>
#include <stdint.h>

// Problem constants (fixed by the reference)
#define BSZ   8
#define CDIM  256
#define NDIM  1024          // 32*32
#define MROWS 8192          // NDIM*BSZ
#define NHEAD 8
#define HIDD  128
#define FFD   512
#define NHYP  3
#define HC    2048          // NHEAD*CDIM
#define NLR   4096          // fused Wl|Wr output width
#define NEG   0.2f
#define EPSLN 1e-5f

// ---------------------------------------------------------------------------
// Static scratch (no allocations allowed)
// ---------------------------------------------------------------------------
__device__ float g_node[MROWS * CDIM];
__device__ float g_adj [MROWS * CDIM];
__device__ float g_orig[MROWS * CDIM];
__device__ float g_tmp [MROWS * CDIM];
__device__ float g_tmp2[2 * MROWS * CDIM];     // GCN GEMM outs: z0=conf, z1=adj
__device__ float g_xlr [(size_t)MROWS * NLR];  // SINGLE hyp buffer, reused (L2-hot)
__device__ float g_blr [NHYP * NLR];

// bf16 (bit-pattern uint16) hi/lo activation buffers (row-major [M][K])
__device__ uint16_t bX0h [MROWS * CDIM], bX0l [MROWS * CDIM];
__device__ uint16_t bNodeh[MROWS * CDIM], bNodel[MROWS * CDIM];
__device__ uint16_t bHidh[MROWS * FFD],  bHidl[MROWS * FFD];
__device__ uint16_t bGateh[2 * MROWS * CDIM], bGatel[2 * MROWS * CDIM]; // z0=xc, z1=xa
__device__ uint16_t bConfh[MROWS * CDIM], bConfl[MROWS * CDIM];
__device__ uint16_t bOrigh[MROWS * CDIM], bOrigl[MROWS * CDIM];
__device__ uint16_t bHid3h[NHYP * MROWS * HIDD], bHid3l[NHYP * MROWS * HIDD];
__device__ uint16_t bFeat3h[NHYP * MROWS * CDIM], bFeat3l[NHYP * MROWS * CDIM];

// weight hi/lo buffers, stored [K][N] N-major (GEMM B operand)
__device__ uint16_t wWph [CDIM*CDIM],  wWpl [CDIM*CDIM];
__device__ uint16_t wWm1h[CDIM*HIDD],  wWm1l[CDIM*HIDD];
__device__ uint16_t wWm2h[HIDD*CDIM],  wWm2l[HIDD*CDIM];
__device__ uint16_t wGh  [2*CDIM*CDIM], wGl [2*CDIM*CDIM];      // z0=Wgcc, z1=Wgca
__device__ uint16_t wWi1h[NHYP*CDIM*HIDD], wWi1l[NHYP*CDIM*HIDD];
__device__ uint16_t wWi2h[NHYP*HIDD*CDIM], wWi2l[NHYP*HIDD*CDIM];
__device__ uint16_t wLRh [NHYP*(size_t)CDIM*NLR], wLRl[NHYP*(size_t)CDIM*NLR];
__device__ uint16_t wWf1h[CDIM*FFD],   wWf1l[CDIM*FFD];
__device__ uint16_t wWf2h[FFD*CDIM],   wWf2l[FFD*CDIM];

// ---------------------------------------------------------------------------
// bf16 split helpers
// ---------------------------------------------------------------------------
__device__ __forceinline__ uint32_t bf16_rn(float f)
{
    uint32_t u = __float_as_uint(f);
    return (u + 0x7FFFu + ((u >> 16) & 1u)) >> 16;
}
__device__ __forceinline__ void bf16_split(float f, uint32_t& h, uint32_t& l)
{
    h = bf16_rn(f);
    float rem = f - __uint_as_float(h << 16);
    l = bf16_rn(rem);
}
__device__ __forceinline__ void store_pair(uint16_t* hi, uint16_t* lo, size_t o,
                                           float v0, float v1)
{
    uint32_t h0, l0, h1, l1;
    bf16_split(v0, h0, l0);
    bf16_split(v1, h1, l1);
    *(uint32_t*)&hi[o] = h0 | (h1 << 16);
    *(uint32_t*)&lo[o] = l0 | (l1 << 16);
}

// ---------------------------------------------------------------------------
// ALL weight conversions in ONE launch (job table by value, blockIdx.y = job)
// ---------------------------------------------------------------------------
#define NJOBS 15
struct ConvJob {
    const float* src;
    uint16_t *hi, *lo;
    int N, LD, off, n4;
};
struct ConvJobs { ConvJob j[NJOBS]; };

__global__ void convert_all_k(ConvJobs jobs)
{
    ConvJob jb = jobs.j[blockIdx.y];
    int i = blockIdx.x * blockDim.x + threadIdx.x;
    if (i >= jb.n4) return;
    int e = i * 4;
    int k = e / jb.N, n = e - k * jb.N;
    float4 q = *(const float4*)(jb.src + e);
    uint32_t h0,h1,h2,h3,l0,l1,l2,l3;
    bf16_split(q.x,h0,l0); bf16_split(q.y,h1,l1);
    bf16_split(q.z,h2,l2); bf16_split(q.w,h3,l3);
    size_t d = (size_t)k * jb.LD + jb.off + n;
    *(uint2*)(jb.hi + d) = make_uint2(h0 | (h1 << 16), h2 | (h3 << 16));
    *(uint2*)(jb.lo + d) = make_uint2(l0 | (l1 << 16), l2 | (l3 << 16));
}

// blr[z][0:HC)=bl[z], blr[z][HC:NLR)=br[z]
__global__ void blr_fill_k(const float* __restrict__ bl, const float* __restrict__ br,
                           float* __restrict__ blr)
{
    int z = blockIdx.x;
    for (int c = threadIdx.x; c < NLR; c += blockDim.x)
        blr[(size_t)z * NLR + c] = (c < HC) ? bl[(size_t)z * HC + c]
                                            : br[(size_t)z * HC + c - HC];
}

// ---------------------------------------------------------------------------
// Transpose: x[B,C,N] -> X0[(n*B+b), C] as bf16 hi/lo.
// Vectorized: each thread owns a c-pair and writes one packed uint32 per array.
// Block (16,32): tx = c-pair index, ty = n index.
// ---------------------------------------------------------------------------
__global__ void transpose_in_k(const float* __restrict__ x,
                               uint16_t* __restrict__ X0h, uint16_t* __restrict__ X0l)
{
    __shared__ float s[32][33];
    int b  = blockIdx.z;
    int c0 = blockIdx.y * 32;
    int n0 = blockIdx.x * 32;
    int tx = threadIdx.x;   // 0..15
    int ty = threadIdx.y;   // 0..31
    const float* xr = x + ((size_t)b * CDIM + (c0 + ty)) * NDIM + n0;
    s[ty][tx]      = xr[tx];
    s[ty][tx + 16] = xr[tx + 16];
    __syncthreads();
    float v0 = s[2 * tx][ty];
    float v1 = s[2 * tx + 1][ty];
    uint32_t h0, l0, h1, l1;
    bf16_split(v0, h0, l0);
    bf16_split(v1, h1, l1);
    size_t o = ((size_t)(n0 + ty) * BSZ + b) * CDIM + c0 + 2 * tx;
    *(uint32_t*)&X0h[o] = h0 | (h1 << 16);
    *(uint32_t*)&X0l[o] = l0 | (l1 << 16);
}

// ---------------------------------------------------------------------------
// mma.sync tensor-core GEMM (proven config: BM=64, BN=128, BK=32, 2-stage).
// 3-term split: AhBh + AhBl + AlBh, fp32 accumulate, z-batched.
// act: 0 fp32(+res), 1 relu->bf16, 2 gate->(C=sig*res, C2=(1-sig)*res),
//      3 fp32+bf16, 4 (bias+res)->bf16
// ---------------------------------------------------------------------------
__device__ __forceinline__ uint32_t sptr(const void* p)
{
    return (uint32_t)__cvta_generic_to_shared(p);
}
__device__ __forceinline__ void cp16_s(uint32_t dst, const void* src)
{
    asm volatile("cp.async.cg.shared.global [%0], [%1], 16;" :: "r"(dst), "l"(src));
}
__device__ __forceinline__ void ldsm4(uint32_t* r, uint32_t addr)
{
    asm volatile("ldmatrix.sync.aligned.m8n8.x4.shared.b16 {%0,%1,%2,%3}, [%4];"
                 : "=r"(r[0]), "=r"(r[1]), "=r"(r[2]), "=r"(r[3]) : "r"(addr));
}
__device__ __forceinline__ void ldsm4t(uint32_t* r, uint32_t addr)
{
    asm volatile("ldmatrix.sync.aligned.m8n8.x4.trans.shared.b16 {%0,%1,%2,%3}, [%4];"
                 : "=r"(r[0]), "=r"(r[1]), "=r"(r[2]), "=r"(r[3]) : "r"(addr));
}
__device__ __forceinline__ void mma16816(float* c, const uint32_t* a, uint32_t b0, uint32_t b1)
{
    asm volatile(
        "mma.sync.aligned.m16n8k16.row.col.f32.bf16.bf16.f32 "
        "{%0,%1,%2,%3}, {%4,%5,%6,%7}, {%8,%9}, {%0,%1,%2,%3};"
        : "+f"(c[0]), "+f"(c[1]), "+f"(c[2]), "+f"(c[3])
        : "r"(a[0]), "r"(a[1]), "r"(a[2]), "r"(a[3]), "r"(b0), "r"(b1));
}

#define GAP  40                       // A smem pitch (elems): 80B rows, conflict-free
#define GBP  136                      // B smem pitch (elems): 272B rows, conflict-free
#define A_SZ (64 * GAP)               // 2560 elems
#define B_SZ (32 * GBP)               // 4352 elems
#define SSTAGE (2 * A_SZ + 2 * B_SZ)  // 13824 elems per stage
#define GSMEM_BYTES (2 * SSTAGE * 2)  // 55296 bytes

__global__ __launch_bounds__(256, 3)
void gemm_k(const uint16_t* __restrict__ Ah, const uint16_t* __restrict__ Al,
            const uint16_t* __restrict__ Bh, const uint16_t* __restrict__ Bl,
            const float* __restrict__ bias, const float* __restrict__ res,
            float* __restrict__ C,
            uint16_t* __restrict__ Chi, uint16_t* __restrict__ Clo,
            uint16_t* __restrict__ C2hi, uint16_t* __restrict__ C2lo,
            int M, int N, int K, int ldb, int act,
            size_t zA, size_t zB, size_t zBias, size_t zC, size_t zRes)
{
    extern __shared__ __align__(16) uint16_t sm[];
    int z = blockIdx.z;
    Ah += z * zA; Al += z * zA;
    Bh += z * zB; Bl += z * zB;
    if (bias) bias += z * zBias;
    if (res)  res  += z * zRes;
    if (C)    C    += z * zC;
    if (Chi)  { Chi  += z * zC; Clo  += z * zC; }
    if (C2hi) { C2hi += z * zC; C2lo += z * zC; }

    int tid = threadIdx.x, wid = tid >> 5, lane = tid & 31;
    int wm = wid & 1, wn = wid >> 1;
    int m0 = blockIdx.y * 64, n0 = blockIdx.x * 128;

    float acc[2][4][4] = {};

    int arow = tid >> 2, akc = (tid & 3) * 8;
    int a_row  = wm * 32 + (lane & 15);
    int a_koff = (lane >> 4) * 8;
    int b_k    = (lane & 7) + (lane & 8);
    int b_n    = wn * 32 + ((lane & 16) >> 1);

    uint32_t smb = sptr(sm);

    auto load_stage = [&](int kt, int st) {
        uint32_t base = smb + st * (SSTAGE * 2);
        int kg = kt * 32;
        size_t ga = (size_t)(m0 + arow) * K + kg + akc;
        uint32_t da = base + (arow * GAP + akc) * 2;
        cp16_s(da,            Ah + ga);
        cp16_s(da + A_SZ * 2, Al + ga);
        #pragma unroll
        for (int v = 0; v < 2; v++) {
            int idx = tid + v * 256;
            int brow = idx >> 4, bnc = (idx & 15) * 8;
            size_t gb = (size_t)(kg + brow) * ldb + n0 + bnc;
            uint32_t db = base + 2 * A_SZ * 2 + (brow * GBP + bnc) * 2;
            cp16_s(db,            Bh + gb);
            cp16_s(db + B_SZ * 2, Bl + gb);
        }
    };

    int KT = K / 32;
    load_stage(0, 0);
    asm volatile("cp.async.commit_group;");

    int buf = 0;
    for (int kt = 0; kt < KT; kt++) {
        if (kt + 1 < KT) {
            load_stage(kt + 1, buf ^ 1);
            asm volatile("cp.async.commit_group;");
            asm volatile("cp.async.wait_group 1;");
        } else {
            asm volatile("cp.async.wait_group 0;");
        }
        __syncthreads();

        uint32_t pAh = smb + buf * (SSTAGE * 2);
        uint32_t pAl = pAh + A_SZ * 2;
        uint32_t pBh = pAh + 2 * A_SZ * 2;
        uint32_t pBl = pBh + B_SZ * 2;

        #pragma unroll
        for (int ks = 0; ks < 2; ks++) {
            uint32_t ah[2][4], al[2][4];
            #pragma unroll
            for (int mf = 0; mf < 2; mf++) {
                uint32_t off = ((a_row + mf * 16) * GAP + ks * 16 + a_koff) * 2;
                ldsm4(ah[mf], pAh + off);
                ldsm4(al[mf], pAl + off);
            }
            #pragma unroll
            for (int nb = 0; nb < 2; nb++) {
                uint32_t bh[4], bl[4];
                uint32_t boff = ((ks * 16 + b_k) * GBP + b_n + nb * 16) * 2;
                ldsm4t(bh, pBh + boff);
                ldsm4t(bl, pBl + boff);
                #pragma unroll
                for (int mf = 0; mf < 2; mf++) {
                    mma16816(acc[mf][2*nb],   ah[mf], bh[0], bh[1]);
                    mma16816(acc[mf][2*nb],   ah[mf], bl[0], bl[1]);
                    mma16816(acc[mf][2*nb],   al[mf], bh[0], bh[1]);
                    mma16816(acc[mf][2*nb+1], ah[mf], bh[2], bh[3]);
                    mma16816(acc[mf][2*nb+1], ah[mf], bl[2], bl[3]);
                    mma16816(acc[mf][2*nb+1], al[mf], bh[2], bh[3]);
                }
            }
        }
        __syncthreads();
        buf ^= 1;
    }

    // ---- epilogue
    int gr = lane >> 2, gc = (lane & 3) * 2;
    #pragma unroll
    for (int mf = 0; mf < 2; mf++) {
        #pragma unroll
        for (int nf = 0; nf < 4; nf++) {
            int n = n0 + wn * 32 + nf * 8 + gc;
            #pragma unroll
            for (int half = 0; half < 2; half++) {
                int m = m0 + wm * 32 + mf * 16 + gr + half * 8;
                size_t o = (size_t)m * N + n;
                float v0 = acc[mf][nf][2*half + 0];
                float v1 = acc[mf][nf][2*half + 1];
                if (bias) { v0 += __ldg(&bias[n]); v1 += __ldg(&bias[n + 1]); }
                if (act == 0) {
                    if (res) { float2 rr = *(const float2*)&res[o]; v0 += rr.x; v1 += rr.y; }
                    *(float2*)&C[o] = make_float2(v0, v1);
                } else if (act == 1) {
                    store_pair(Chi, Clo, o, fmaxf(v0, 0.f), fmaxf(v1, 0.f));
                } else if (act == 2) {
                    float2 nd = *(const float2*)&res[o];
                    float s0 = 1.f / (1.f + expf(-v0));
                    float s1 = 1.f / (1.f + expf(-v1));
                    store_pair(Chi,  Clo,  o, s0 * nd.x, s1 * nd.y);
                    store_pair(C2hi, C2lo, o, (1.f - s0) * nd.x, (1.f - s1) * nd.y);
                } else if (act == 3) {
                    *(float2*)&C[o] = make_float2(v0, v1);
                    store_pair(Chi, Clo, o, v0, v1);
                } else { // act == 4
                    float2 rr = *(const float2*)&res[o];
                    store_pair(Chi, Clo, o, v0 + rr.x, v1 + rr.y);
                }
            }
        }
    }
}

// ---------------------------------------------------------------------------
// Block-wide sum over 256 threads
// ---------------------------------------------------------------------------
__device__ __forceinline__ float bsum256(float v)
{
    __shared__ float s[256];
    int t = threadIdx.x;
    s[t] = v; __syncthreads();
    #pragma unroll
    for (int o = 128; o > 0; o >>= 1) {
        if (t < o) s[t] += s[t + o];
        __syncthreads();
    }
    float r = s[0];
    __syncthreads();
    return r;
}

__device__ __forceinline__ float grid_deg(int i, int j)
{
    return 1.f + (i > 0) + (i < 31) + (j > 0) + (j < 31);
}

// ---------------------------------------------------------------------------
// Fused GCN aggregation + bias + LayerNorm.
// ---------------------------------------------------------------------------
__global__ __launch_bounds__(256)
void gcn_ln_k(const float* __restrict__ hw, const float* __restrict__ bg,
              const float* __restrict__ gamma, const float* __restrict__ beta,
              float* __restrict__ out_f32,
              uint16_t* __restrict__ out_hi, uint16_t* __restrict__ out_lo,
              const float* __restrict__ addin, float* __restrict__ out2_f32,
              uint16_t* __restrict__ out2_hi, uint16_t* __restrict__ out2_lo)
{
    int r = blockIdx.x;
    int n = r >> 3, b = r & 7;
    int i = n >> 5, j = n & 31;
    float degn = grid_deg(i, j);

    int   nbr[5];
    float nrm[5];
    nbr[0] = n;                       nrm[0] = 1.f / degn;
    nbr[1] = (i > 0)  ? n - 32 : n;
    nbr[2] = (i < 31) ? n + 32 : n;
    nbr[3] = (j > 0)  ? n - 1  : n;
    nbr[4] = (j < 31) ? n + 1  : n;
    bool vld[5] = { true, i > 0, i < 31, j > 0, j < 31 };
    #pragma unroll
    for (int t = 1; t < 5; t++) {
        int m = nbr[t];
        float degm = grid_deg(m >> 5, m & 31);
        nrm[t] = vld[t] ? rsqrtf(degm * degn) : 0.f;
    }

    int c = threadIdx.x;
    float acc = bg[c];
    #pragma unroll
    for (int t = 0; t < 5; t++)
        acc += nrm[t] * hw[((size_t)nbr[t] * BSZ + b) * CDIM + c];

    float mean = bsum256(acc) * (1.f / CDIM);
    float d = acc - mean;
    float var = bsum256(d * d) * (1.f / CDIM);
    float o = d * rsqrtf(var + EPSLN) * gamma[c] + beta[c];
    size_t idx = (size_t)r * CDIM + c;

    if (out_f32) out_f32[idx] = o;
    if (out_hi) {
        uint32_t h, l; bf16_split(o, h, l);
        out_hi[idx] = (uint16_t)h; out_lo[idx] = (uint16_t)l;
    }
    if (addin) {
        float o2 = o + addin[idx];
        out2_f32[idx] = o2;
        uint32_t h, l; bf16_split(o2, h, l);
        out2_hi[idx] = (uint16_t)h; out2_lo[idx] = (uint16_t)l;
    }
}

// ---------------------------------------------------------------------------
// Final residual LayerNorm, writing image layout out[b,c,n]
// ---------------------------------------------------------------------------
__global__ __launch_bounds__(256)
void ln_out_k(const float* __restrict__ in, const float* __restrict__ gamma,
              const float* __restrict__ beta, float* __restrict__ outp)
{
    int r = blockIdx.x;
    int n = r >> 3, b = r & 7;
    int c = threadIdx.x;
    float v = in[(size_t)r * CDIM + c];
    float mean = bsum256(v) * (1.f / CDIM);
    float d = v - mean;
    float var = bsum256(d * d) * (1.f / CDIM);
    outp[(size_t)b * (CDIM * NDIM) + (size_t)c * NDIM + n] =
        d * rsqrtf(var + EPSLN) * gamma[c] + beta[c];
}

// ---------------------------------------------------------------------------
// GATv2 aggregation for ONE hypothesis (pointers pre-offset on host).
// Per-warp private partial sums + 8-way tree reduce.
// ---------------------------------------------------------------------------
__global__ __launch_bounds__(256)
void gat_k(const float* __restrict__ base, const float* __restrict__ att,
           const float* __restrict__ gbias, float* __restrict__ outp)
{
    __shared__ float sacc[NHEAD][CDIM];

    int r = blockIdx.x;
    int n = r >> 3, b = r & 7;
    int i = n >> 5, j = n & 31;

    int nbr[5];
    nbr[0] = n;
    nbr[1] = (i > 0)  ? n - 32 : n;
    nbr[2] = (i < 31) ? n + 32 : n;
    nbr[3] = (j > 0)  ? n - 1  : n;
    nbr[4] = (j < 31) ? n + 1  : n;
    bool vld[5] = { true, i > 0, i < 31, j > 0, j < 31 };

    int wid = threadIdx.x >> 5, lane = threadIdx.x & 31;
    const float* xrp  = base + ((size_t)n * BSZ + b) * NLR + HC + wid * CDIM + lane;
    const float* attp = att + wid * CDIM + lane;

    float xrv[8], attv[8];
    #pragma unroll
    for (int t = 0; t < 8; t++) { xrv[t] = xrp[32 * t]; attv[t] = attp[32 * t]; }

    float xlv[5][8], logit[5];
    #pragma unroll
    for (int m = 0; m < 5; m++) {
        const float* xlp = base + ((size_t)nbr[m] * BSZ + b) * NLR + wid * CDIM + lane;
        float s = 0.f;
        #pragma unroll
        for (int t = 0; t < 8; t++) {
            float v = xlp[32 * t];
            xlv[m][t] = v;
            float e = v + xrv[t];
            e = e > 0.f ? e : NEG * e;
            s += e * attv[t];
        }
        #pragma unroll
        for (int o = 16; o > 0; o >>= 1) s += __shfl_xor_sync(0xffffffffu, s, o);
        logit[m] = vld[m] ? s : -1e30f;
    }

    float mx = logit[0];
    #pragma unroll
    for (int m = 1; m < 5; m++) mx = fmaxf(mx, logit[m]);
    float alpha[5], ssum = 0.f;
    #pragma unroll
    for (int m = 0; m < 5; m++) { alpha[m] = expf(logit[m] - mx); ssum += alpha[m]; }
    float scale = 1.f / (ssum * NHEAD);

    #pragma unroll
    for (int t = 0; t < 8; t++) {
        float o = 0.f;
        #pragma unroll
        for (int m = 0; m < 5; m++) o += alpha[m] * xlv[m][t];
        sacc[wid][lane + 32 * t] = o * scale;
    }
    __syncthreads();

    int c = threadIdx.x;
    float s = sacc[0][c];
    #pragma unroll
    for (int w = 1; w < NHEAD; w++) s += sacc[w][c];
    outp[(size_t)b * (CDIM * NDIM) + (size_t)c * NDIM + n] = s + gbias[c];
}

// ---------------------------------------------------------------------------
// Host
// ---------------------------------------------------------------------------
static void gemm(const uint16_t* Ah, const uint16_t* Al,
                 const uint16_t* Bh, const uint16_t* Bl, int ldb,
                 const float* bias, const float* res,
                 float* C, uint16_t* Chi, uint16_t* Clo,
                 uint16_t* C2hi, uint16_t* C2lo,
                 int M, int N, int K, int act, int Z,
                 size_t zA, size_t zB, size_t zBias, size_t zC, size_t zRes)
{
    cudaFuncSetAttribute(gemm_k, cudaFuncAttributeMaxDynamicSharedMemorySize, GSMEM_BYTES);
    gemm_k<<<dim3(N / 128, M / 64, Z), 256, GSMEM_BYTES>>>(
        Ah, Al, Bh, Bl, bias, res, C, Chi, Clo, C2hi, C2lo,
        M, N, K, ldb, act, zA, zB, zBias, zC, zRes);
}

extern "C" void kernel_launch(void* const* d_in, const int* in_sizes, int n_in,
                              void* d_out, int out_size)
{
    const float* x    = (const float*)d_in[0];
    // d_in[1] = edge_index (int64) — fixed 32x32 grid; computed analytically.
    const float* Wp   = (const float*)d_in[2];
    const float* bp   = (const float*)d_in[3];
    const float* Wm1  = (const float*)d_in[4];
    const float* bm1  = (const float*)d_in[5];
    const float* Wm2  = (const float*)d_in[6];
    const float* bm2  = (const float*)d_in[7];
    const float* Wgca = (const float*)d_in[8];
    const float* bgca = (const float*)d_in[9];
    const float* Wgcc = (const float*)d_in[10];
    const float* bgcc = (const float*)d_in[11];
    const float* Wi1  = (const float*)d_in[12];
    const float* bi1  = (const float*)d_in[13];
    const float* Wi2  = (const float*)d_in[14];
    const float* bi2  = (const float*)d_in[15];
    const float* Wl   = (const float*)d_in[16];
    const float* bl   = (const float*)d_in[17];
    const float* Wr   = (const float*)d_in[18];
    const float* br   = (const float*)d_in[19];
    const float* att  = (const float*)d_in[20];
    const float* gbia = (const float*)d_in[21];
    const float* Wf1  = (const float*)d_in[22];
    const float* bf1  = (const float*)d_in[23];
    const float* Wf2  = (const float*)d_in[24];
    const float* bf2  = (const float*)d_in[25];
    const float* lng  = (const float*)d_in[26];
    const float* lnb  = (const float*)d_in[27];
    float* out = (float*)d_out;

    float *pNode, *pAdj, *pOrig, *pTmp, *pTmp2, *pXlr, *pBlr;
    cudaGetSymbolAddress((void**)&pNode, g_node);
    cudaGetSymbolAddress((void**)&pAdj,  g_adj);
    cudaGetSymbolAddress((void**)&pOrig, g_orig);
    cudaGetSymbolAddress((void**)&pTmp,  g_tmp);
    cudaGetSymbolAddress((void**)&pTmp2, g_tmp2);
    cudaGetSymbolAddress((void**)&pXlr,  g_xlr);
    cudaGetSymbolAddress((void**)&pBlr,  g_blr);

    uint16_t *X0h,*X0l,*Nodeh,*Nodel,*Hidh,*Hidl,*Gateh,*Gatel,*Confh,*Confl;
    uint16_t *Origh,*Origl,*Hid3h,*Hid3l,*Feat3h,*Feat3l;
    cudaGetSymbolAddress((void**)&X0h, bX0h);     cudaGetSymbolAddress((void**)&X0l, bX0l);
    cudaGetSymbolAddress((void**)&Nodeh, bNodeh); cudaGetSymbolAddress((void**)&Nodel, bNodel);
    cudaGetSymbolAddress((void**)&Hidh, bHidh);   cudaGetSymbolAddress((void**)&Hidl, bHidl);
    cudaGetSymbolAddress((void**)&Gateh, bGateh); cudaGetSymbolAddress((void**)&Gatel, bGatel);
    cudaGetSymbolAddress((void**)&Confh, bConfh); cudaGetSymbolAddress((void**)&Confl, bConfl);
    cudaGetSymbolAddress((void**)&Origh, bOrigh); cudaGetSymbolAddress((void**)&Origl, bOrigl);
    cudaGetSymbolAddress((void**)&Hid3h, bHid3h); cudaGetSymbolAddress((void**)&Hid3l, bHid3l);
    cudaGetSymbolAddress((void**)&Feat3h, bFeat3h); cudaGetSymbolAddress((void**)&Feat3l, bFeat3l);

    uint16_t *Wph,*Wpl,*Wm1h,*Wm1l,*Wm2h,*Wm2l,*Gh,*Gl,*Wi1h,*Wi1l,*Wi2h,*Wi2l;
    uint16_t *LRh,*LRl,*Wf1h,*Wf1l,*Wf2h,*Wf2l;
    cudaGetSymbolAddress((void**)&Wph, wWph);   cudaGetSymbolAddress((void**)&Wpl, wWpl);
    cudaGetSymbolAddress((void**)&Wm1h, wWm1h); cudaGetSymbolAddress((void**)&Wm1l, wWm1l);
    cudaGetSymbolAddress((void**)&Wm2h, wWm2h); cudaGetSymbolAddress((void**)&Wm2l, wWm2l);
    cudaGetSymbolAddress((void**)&Gh, wGh);     cudaGetSymbolAddress((void**)&Gl, wGl);
    cudaGetSymbolAddress((void**)&Wi1h, wWi1h); cudaGetSymbolAddress((void**)&Wi1l, wWi1l);
    cudaGetSymbolAddress((void**)&Wi2h, wWi2h); cudaGetSymbolAddress((void**)&Wi2l, wWi2l);
    cudaGetSymbolAddress((void**)&LRh, wLRh);   cudaGetSymbolAddress((void**)&LRl, wLRl);
    cudaGetSymbolAddress((void**)&Wf1h, wWf1h); cudaGetSymbolAddress((void**)&Wf1l, wWf1l);
    cudaGetSymbolAddress((void**)&Wf2h, wWf2h); cudaGetSymbolAddress((void**)&Wf2l, wWf2l);

    const size_t OUTSZ = (size_t)BSZ * CDIM * NDIM;

    // 0. ALL weight conversions in ONE launch (15 jobs incl. Wf1/Wf2)
    ConvJobs jobs;
    int ji = 0;
    auto addjob = [&](const float* s, uint16_t* h, uint16_t* l, int N, int LD, int off, int total) {
        jobs.j[ji++] = ConvJob{ s, h, l, N, LD, off, total / 4 };
    };
    addjob(Wp,   Wph,  Wpl,  CDIM, CDIM, 0, CDIM * CDIM);
    addjob(Wm1,  Wm1h, Wm1l, HIDD, HIDD, 0, CDIM * HIDD);
    addjob(Wm2,  Wm2h, Wm2l, CDIM, CDIM, 0, HIDD * CDIM);
    addjob(Wgcc, Gh,               Gl,               CDIM, CDIM, 0, CDIM * CDIM);
    addjob(Wgca, Gh + CDIM * CDIM, Gl + CDIM * CDIM, CDIM, CDIM, 0, CDIM * CDIM);
    addjob(Wi1,  Wi1h, Wi1l, HIDD, HIDD, 0, NHYP * CDIM * HIDD);
    addjob(Wi2,  Wi2h, Wi2l, CDIM, CDIM, 0, NHYP * HIDD * CDIM);
    for (int z = 0; z < NHYP; z++) {
        size_t ws = (size_t)z * CDIM * HC, wd = (size_t)z * CDIM * NLR;
        addjob(Wl + ws, LRh + wd, LRl + wd, HC, NLR, 0,  CDIM * HC);
        addjob(Wr + ws, LRh + wd, LRl + wd, HC, NLR, HC, CDIM * HC);
    }
    addjob(Wf1, Wf1h, Wf1l, FFD,  FFD,  0, CDIM * FFD);
    addjob(Wf2, Wf2h, Wf2l, CDIM, CDIM, 0, FFD * CDIM);
    convert_all_k<<<dim3(512, NJOBS), 256>>>(jobs);
    blr_fill_k<<<NHYP, 256>>>(bl, br, pBlr);

    // 1. x -> X0 (bf16 hi/lo), vectorized u32 stores
    transpose_in_k<<<dim3(NDIM / 32, CDIM / 32, BSZ), dim3(16, 32)>>>(x, X0h, X0l);

    // 2. node = X0 @ Wp + bp  (fp32 + bf16)
    gemm(X0h, X0l, Wph, Wpl, CDIM, bp, nullptr,
         pNode, Nodeh, Nodel, nullptr, nullptr, MROWS, CDIM, CDIM, 3, 1, 0,0,0,0,0);

    // 3. hid = relu(node@Wm1+bm1); gate fused into Wm2 epilogue
    gemm(Nodeh, Nodel, Wm1h, Wm1l, HIDD, bm1, nullptr,
         nullptr, Hidh, Hidl, nullptr, nullptr, MROWS, HIDD, CDIM, 1, 1, 0,0,0,0,0);
    gemm(Hidh, Hidl, Wm2h, Wm2l, CDIM, bm2, pNode,
         nullptr, Gateh, Gatel, Gateh + (size_t)MROWS * CDIM, Gatel + (size_t)MROWS * CDIM,
         MROWS, CDIM, HIDD, 2, 1, 0,0,0,0,0);

    // 4. GCN GEMMs batched (z0: xc@Wgcc, z1: xa@Wgca) then the two LN kernels
    gemm(Gateh, Gatel, Gh, Gl, CDIM, nullptr, nullptr,
         pTmp2, nullptr, nullptr, nullptr, nullptr, MROWS, CDIM, CDIM, 0, 2,
         (size_t)MROWS * CDIM, (size_t)CDIM * CDIM, 0, (size_t)MROWS * CDIM, 0);
    gcn_ln_k<<<MROWS, CDIM>>>(pTmp2 + (size_t)MROWS * CDIM, bgca,
                              lng + 0 * CDIM, lnb + 0 * CDIM,
                              pAdj, nullptr, nullptr,
                              nullptr, nullptr, nullptr, nullptr);
    gcn_ln_k<<<MROWS, CDIM>>>(pTmp2, bgcc, lng + 1 * CDIM, lnb + 1 * CDIM,
                              nullptr, Confh, Confl,
                              pAdj, pOrig, Origh, Origl);

    // 5. hypotheses: interv chain z-batched; LR (BM=64) + gat interleaved per
    //    hyp so the single xlr buffer stays L2-hot between producer/consumer
    gemm(Confh, Confl, Wi1h, Wi1l, HIDD, bi1, nullptr,
         nullptr, Hid3h, Hid3l, nullptr, nullptr, MROWS, HIDD, CDIM, 1, NHYP,
         0, (size_t)CDIM * HIDD, HIDD, (size_t)MROWS * HIDD, 0);
    gemm(Hid3h, Hid3l, Wi2h, Wi2l, CDIM, bi2, pOrig,
         nullptr, Feat3h, Feat3l, nullptr, nullptr, MROWS, CDIM, HIDD, 4, NHYP,
         (size_t)MROWS * HIDD, (size_t)HIDD * CDIM, CDIM, (size_t)MROWS * CDIM, 0);
    for (int h = 0; h < NHYP; h++) {
        gemm(Feat3h + (size_t)h * MROWS * CDIM, Feat3l + (size_t)h * MROWS * CDIM,
             LRh + (size_t)h * CDIM * NLR, LRl + (size_t)h * CDIM * NLR, NLR,
             pBlr + (size_t)h * NLR, nullptr,
             pXlr, nullptr, nullptr, nullptr, nullptr, MROWS, NLR, CDIM, 0, 1,
             0, 0, 0, 0, 0);
        gat_k<<<MROWS, 256>>>(pXlr, att + (size_t)h * HC,
                              gbia + (size_t)h * CDIM, out + (size_t)h * OUTSZ);
    }

    // 6. FFN + residual LN -> output slot 3
    gemm(Origh, Origl, Wf1h, Wf1l, FFD, bf1, nullptr,
         nullptr, Hidh, Hidl, nullptr, nullptr, MROWS, FFD, CDIM, 1, 1, 0,0,0,0,0);
    gemm(Hidh, Hidl, Wf2h, Wf2l, CDIM, bf2, pOrig,
         pTmp, nullptr, nullptr, nullptr, nullptr, MROWS, CDIM, FFD, 0, 1, 0,0,0,0,0);
    ln_out_k<<<MROWS, CDIM>>>(pTmp, lng + 2 * CDIM, lnb + 2 * CDIM, out + 3 * OUTSZ);
}

// round 17
// speedup vs baseline: 1.0330x; 1.0065x over previous
#include <cuda_runtime.h>
#include <math.h>
#include <stdint.h>

// Problem constants (fixed by the reference)
#define BSZ   8
#define CDIM  256
#define NDIM  1024          // 32*32
#define MROWS 8192          // NDIM*BSZ
#define NHEAD 8
#define HIDD  128
#define FFD   512
#define NHYP  3
#define HC    2048          // NHEAD*CDIM
#define NLR   4096          // fused Wl|Wr output width
#define NEG   0.2f
#define EPSLN 1e-5f

// ---------------------------------------------------------------------------
// Static scratch (no allocations allowed)
// ---------------------------------------------------------------------------
__device__ float g_node[MROWS * CDIM];
__device__ float g_orig[MROWS * CDIM];
__device__ float g_tmp [MROWS * CDIM];
__device__ float g_tmp2[2 * MROWS * CDIM];     // GCN GEMM outs: z0=conf, z1=adj
__device__ float g_xlr [(size_t)MROWS * NLR];  // SINGLE hyp buffer, reused (L2-hot)
__device__ float g_blr [NHYP * NLR];

// bf16 (bit-pattern uint16) hi/lo activation buffers (row-major [M][K])
__device__ uint16_t bX0h [MROWS * CDIM], bX0l [MROWS * CDIM];
__device__ uint16_t bNodeh[MROWS * CDIM], bNodel[MROWS * CDIM];
__device__ uint16_t bHidh[MROWS * FFD],  bHidl[MROWS * FFD];
__device__ uint16_t bGateh[2 * MROWS * CDIM], bGatel[2 * MROWS * CDIM]; // z0=xc, z1=xa
__device__ uint16_t bConfh[MROWS * CDIM], bConfl[MROWS * CDIM];
__device__ uint16_t bOrigh[MROWS * CDIM], bOrigl[MROWS * CDIM];
__device__ uint16_t bHid3h[NHYP * MROWS * HIDD], bHid3l[NHYP * MROWS * HIDD];
__device__ uint16_t bFeat3h[NHYP * MROWS * CDIM], bFeat3l[NHYP * MROWS * CDIM];

// weight hi/lo buffers, stored [K][N] N-major (GEMM B operand)
__device__ uint16_t wWph [CDIM*CDIM],  wWpl [CDIM*CDIM];
__device__ uint16_t wWm1h[CDIM*HIDD],  wWm1l[CDIM*HIDD];
__device__ uint16_t wWm2h[HIDD*CDIM],  wWm2l[HIDD*CDIM];
__device__ uint16_t wGh  [2*CDIM*CDIM], wGl [2*CDIM*CDIM];      // z0=Wgcc, z1=Wgca
__device__ uint16_t wWi1h[NHYP*CDIM*HIDD], wWi1l[NHYP*CDIM*HIDD];
__device__ uint16_t wWi2h[NHYP*HIDD*CDIM], wWi2l[NHYP*HIDD*CDIM];
__device__ uint16_t wLRh [NHYP*(size_t)CDIM*NLR], wLRl[NHYP*(size_t)CDIM*NLR];
__device__ uint16_t wWf1h[CDIM*FFD],   wWf1l[CDIM*FFD];
__device__ uint16_t wWf2h[FFD*CDIM],   wWf2l[FFD*CDIM];

// ---------------------------------------------------------------------------
// bf16 split helpers
// ---------------------------------------------------------------------------
__device__ __forceinline__ uint32_t bf16_rn(float f)
{
    uint32_t u = __float_as_uint(f);
    return (u + 0x7FFFu + ((u >> 16) & 1u)) >> 16;
}
__device__ __forceinline__ void bf16_split(float f, uint32_t& h, uint32_t& l)
{
    h = bf16_rn(f);
    float rem = f - __uint_as_float(h << 16);
    l = bf16_rn(rem);
}
__device__ __forceinline__ void store_pair(uint16_t* hi, uint16_t* lo, size_t o,
                                           float v0, float v1)
{
    uint32_t h0, l0, h1, l1;
    bf16_split(v0, h0, l0);
    bf16_split(v1, h1, l1);
    *(uint32_t*)&hi[o] = h0 | (h1 << 16);
    *(uint32_t*)&lo[o] = l0 | (l1 << 16);
}

// ---------------------------------------------------------------------------
// ALL weight conversions in ONE launch (job table by value, blockIdx.y = job)
// ---------------------------------------------------------------------------
#define NJOBS 15
struct ConvJob {
    const float* src;
    uint16_t *hi, *lo;
    int N, LD, off, n4;
};
struct ConvJobs { ConvJob j[NJOBS]; };

__global__ void convert_all_k(ConvJobs jobs)
{
    ConvJob jb = jobs.j[blockIdx.y];
    int i = blockIdx.x * blockDim.x + threadIdx.x;
    if (i >= jb.n4) return;
    int e = i * 4;
    int k = e / jb.N, n = e - k * jb.N;
    float4 q = *(const float4*)(jb.src + e);
    uint32_t h0,h1,h2,h3,l0,l1,l2,l3;
    bf16_split(q.x,h0,l0); bf16_split(q.y,h1,l1);
    bf16_split(q.z,h2,l2); bf16_split(q.w,h3,l3);
    size_t d = (size_t)k * jb.LD + jb.off + n;
    *(uint2*)(jb.hi + d) = make_uint2(h0 | (h1 << 16), h2 | (h3 << 16));
    *(uint2*)(jb.lo + d) = make_uint2(l0 | (l1 << 16), l2 | (l3 << 16));
}

// blr[z][0:HC)=bl[z], blr[z][HC:NLR)=br[z]
__global__ void blr_fill_k(const float* __restrict__ bl, const float* __restrict__ br,
                           float* __restrict__ blr)
{
    int z = blockIdx.x;
    for (int c = threadIdx.x; c < NLR; c += blockDim.x)
        blr[(size_t)z * NLR + c] = (c < HC) ? bl[(size_t)z * HC + c]
                                            : br[(size_t)z * HC + c - HC];
}

// ---------------------------------------------------------------------------
// Transpose: x[B,C,N] -> X0[(n*B+b), C] as bf16 hi/lo (vectorized u32 stores)
// ---------------------------------------------------------------------------
__global__ void transpose_in_k(const float* __restrict__ x,
                               uint16_t* __restrict__ X0h, uint16_t* __restrict__ X0l)
{
    __shared__ float s[32][33];
    int b  = blockIdx.z;
    int c0 = blockIdx.y * 32;
    int n0 = blockIdx.x * 32;
    int tx = threadIdx.x;   // 0..15
    int ty = threadIdx.y;   // 0..31
    const float* xr = x + ((size_t)b * CDIM + (c0 + ty)) * NDIM + n0;
    s[ty][tx]      = xr[tx];
    s[ty][tx + 16] = xr[tx + 16];
    __syncthreads();
    float v0 = s[2 * tx][ty];
    float v1 = s[2 * tx + 1][ty];
    uint32_t h0, l0, h1, l1;
    bf16_split(v0, h0, l0);
    bf16_split(v1, h1, l1);
    size_t o = ((size_t)(n0 + ty) * BSZ + b) * CDIM + c0 + 2 * tx;
    *(uint32_t*)&X0h[o] = h0 | (h1 << 16);
    *(uint32_t*)&X0l[o] = l0 | (l1 << 16);
}

// ---------------------------------------------------------------------------
// mma.sync tensor-core GEMM (proven config: BM=64, BN=128, BK=32, 2-stage).
// 3-term split: AhBh + AhBl + AlBh, fp32 accumulate, z-batched.
// act: 0 fp32(+res), 1 relu->bf16, 2 gate->(C=sig*res, C2=(1-sig)*res),
//      3 fp32+bf16, 4 (bias+res)->bf16
// ---------------------------------------------------------------------------
__device__ __forceinline__ uint32_t sptr(const void* p)
{
    return (uint32_t)__cvta_generic_to_shared(p);
}
__device__ __forceinline__ void cp16_s(uint32_t dst, const void* src)
{
    asm volatile("cp.async.cg.shared.global [%0], [%1], 16;" :: "r"(dst), "l"(src));
}
__device__ __forceinline__ void ldsm4(uint32_t* r, uint32_t addr)
{
    asm volatile("ldmatrix.sync.aligned.m8n8.x4.shared.b16 {%0,%1,%2,%3}, [%4];"
                 : "=r"(r[0]), "=r"(r[1]), "=r"(r[2]), "=r"(r[3]) : "r"(addr));
}
__device__ __forceinline__ void ldsm4t(uint32_t* r, uint32_t addr)
{
    asm volatile("ldmatrix.sync.aligned.m8n8.x4.trans.shared.b16 {%0,%1,%2,%3}, [%4];"
                 : "=r"(r[0]), "=r"(r[1]), "=r"(r[2]), "=r"(r[3]) : "r"(addr));
}
__device__ __forceinline__ void mma16816(float* c, const uint32_t* a, uint32_t b0, uint32_t b1)
{
    asm volatile(
        "mma.sync.aligned.m16n8k16.row.col.f32.bf16.bf16.f32 "
        "{%0,%1,%2,%3}, {%4,%5,%6,%7}, {%8,%9}, {%0,%1,%2,%3};"
        : "+f"(c[0]), "+f"(c[1]), "+f"(c[2]), "+f"(c[3])
        : "r"(a[0]), "r"(a[1]), "r"(a[2]), "r"(a[3]), "r"(b0), "r"(b1));
}

#define GAP  40                       // A smem pitch (elems): 80B rows, conflict-free
#define GBP  136                      // B smem pitch (elems): 272B rows, conflict-free
#define A_SZ (64 * GAP)               // 2560 elems
#define B_SZ (32 * GBP)               // 4352 elems
#define SSTAGE (2 * A_SZ + 2 * B_SZ)  // 13824 elems per stage
#define GSMEM_BYTES (2 * SSTAGE * 2)  // 55296 bytes

__global__ __launch_bounds__(256, 3)
void gemm_k(const uint16_t* __restrict__ Ah, const uint16_t* __restrict__ Al,
            const uint16_t* __restrict__ Bh, const uint16_t* __restrict__ Bl,
            const float* __restrict__ bias, const float* __restrict__ res,
            float* __restrict__ C,
            uint16_t* __restrict__ Chi, uint16_t* __restrict__ Clo,
            uint16_t* __restrict__ C2hi, uint16_t* __restrict__ C2lo,
            int M, int N, int K, int ldb, int act,
            size_t zA, size_t zB, size_t zBias, size_t zC, size_t zRes)
{
    extern __shared__ __align__(16) uint16_t sm[];
    int z = blockIdx.z;
    Ah += z * zA; Al += z * zA;
    Bh += z * zB; Bl += z * zB;
    if (bias) bias += z * zBias;
    if (res)  res  += z * zRes;
    if (C)    C    += z * zC;
    if (Chi)  { Chi  += z * zC; Clo  += z * zC; }
    if (C2hi) { C2hi += z * zC; C2lo += z * zC; }

    int tid = threadIdx.x, wid = tid >> 5, lane = tid & 31;
    int wm = wid & 1, wn = wid >> 1;
    int m0 = blockIdx.y * 64, n0 = blockIdx.x * 128;

    float acc[2][4][4] = {};

    int arow = tid >> 2, akc = (tid & 3) * 8;
    int a_row  = wm * 32 + (lane & 15);
    int a_koff = (lane >> 4) * 8;
    int b_k    = (lane & 7) + (lane & 8);
    int b_n    = wn * 32 + ((lane & 16) >> 1);

    uint32_t smb = sptr(sm);

    auto load_stage = [&](int kt, int st) {
        uint32_t base = smb + st * (SSTAGE * 2);
        int kg = kt * 32;
        size_t ga = (size_t)(m0 + arow) * K + kg + akc;
        uint32_t da = base + (arow * GAP + akc) * 2;
        cp16_s(da,            Ah + ga);
        cp16_s(da + A_SZ * 2, Al + ga);
        #pragma unroll
        for (int v = 0; v < 2; v++) {
            int idx = tid + v * 256;
            int brow = idx >> 4, bnc = (idx & 15) * 8;
            size_t gb = (size_t)(kg + brow) * ldb + n0 + bnc;
            uint32_t db = base + 2 * A_SZ * 2 + (brow * GBP + bnc) * 2;
            cp16_s(db,            Bh + gb);
            cp16_s(db + B_SZ * 2, Bl + gb);
        }
    };

    int KT = K / 32;
    load_stage(0, 0);
    asm volatile("cp.async.commit_group;");

    int buf = 0;
    for (int kt = 0; kt < KT; kt++) {
        if (kt + 1 < KT) {
            load_stage(kt + 1, buf ^ 1);
            asm volatile("cp.async.commit_group;");
            asm volatile("cp.async.wait_group 1;");
        } else {
            asm volatile("cp.async.wait_group 0;");
        }
        __syncthreads();

        uint32_t pAh = smb + buf * (SSTAGE * 2);
        uint32_t pAl = pAh + A_SZ * 2;
        uint32_t pBh = pAh + 2 * A_SZ * 2;
        uint32_t pBl = pBh + B_SZ * 2;

        #pragma unroll
        for (int ks = 0; ks < 2; ks++) {
            uint32_t ah[2][4], al[2][4];
            #pragma unroll
            for (int mf = 0; mf < 2; mf++) {
                uint32_t off = ((a_row + mf * 16) * GAP + ks * 16 + a_koff) * 2;
                ldsm4(ah[mf], pAh + off);
                ldsm4(al[mf], pAl + off);
            }
            #pragma unroll
            for (int nb = 0; nb < 2; nb++) {
                uint32_t bh[4], bl[4];
                uint32_t boff = ((ks * 16 + b_k) * GBP + b_n + nb * 16) * 2;
                ldsm4t(bh, pBh + boff);
                ldsm4t(bl, pBl + boff);
                #pragma unroll
                for (int mf = 0; mf < 2; mf++) {
                    mma16816(acc[mf][2*nb],   ah[mf], bh[0], bh[1]);
                    mma16816(acc[mf][2*nb],   ah[mf], bl[0], bl[1]);
                    mma16816(acc[mf][2*nb],   al[mf], bh[0], bh[1]);
                    mma16816(acc[mf][2*nb+1], ah[mf], bh[2], bh[3]);
                    mma16816(acc[mf][2*nb+1], ah[mf], bl[2], bl[3]);
                    mma16816(acc[mf][2*nb+1], al[mf], bh[2], bh[3]);
                }
            }
        }
        __syncthreads();
        buf ^= 1;
    }

    // ---- epilogue
    int gr = lane >> 2, gc = (lane & 3) * 2;
    #pragma unroll
    for (int mf = 0; mf < 2; mf++) {
        #pragma unroll
        for (int nf = 0; nf < 4; nf++) {
            int n = n0 + wn * 32 + nf * 8 + gc;
            #pragma unroll
            for (int half = 0; half < 2; half++) {
                int m = m0 + wm * 32 + mf * 16 + gr + half * 8;
                size_t o = (size_t)m * N + n;
                float v0 = acc[mf][nf][2*half + 0];
                float v1 = acc[mf][nf][2*half + 1];
                if (bias) { v0 += __ldg(&bias[n]); v1 += __ldg(&bias[n + 1]); }
                if (act == 0) {
                    if (res) { float2 rr = *(const float2*)&res[o]; v0 += rr.x; v1 += rr.y; }
                    *(float2*)&C[o] = make_float2(v0, v1);
                } else if (act == 1) {
                    store_pair(Chi, Clo, o, fmaxf(v0, 0.f), fmaxf(v1, 0.f));
                } else if (act == 2) {
                    float2 nd = *(const float2*)&res[o];
                    float s0 = 1.f / (1.f + expf(-v0));
                    float s1 = 1.f / (1.f + expf(-v1));
                    store_pair(Chi,  Clo,  o, s0 * nd.x, s1 * nd.y);
                    store_pair(C2hi, C2lo, o, (1.f - s0) * nd.x, (1.f - s1) * nd.y);
                } else if (act == 3) {
                    *(float2*)&C[o] = make_float2(v0, v1);
                    store_pair(Chi, Clo, o, v0, v1);
                } else { // act == 4
                    float2 rr = *(const float2*)&res[o];
                    store_pair(Chi, Clo, o, v0 + rr.x, v1 + rr.y);
                }
            }
        }
    }
}

// ---------------------------------------------------------------------------
// Block-wide sum over 256 threads
// ---------------------------------------------------------------------------
__device__ __forceinline__ float bsum256(float v)
{
    __shared__ float s[256];
    int t = threadIdx.x;
    s[t] = v; __syncthreads();
    #pragma unroll
    for (int o = 128; o > 0; o >>= 1) {
        if (t < o) s[t] += s[t + o];
        __syncthreads();
    }
    float r = s[0];
    __syncthreads();
    return r;
}

__device__ __forceinline__ float grid_deg(int i, int j)
{
    return 1.f + (i > 0) + (i < 31) + (j > 0) + (j < 31);
}

// ---------------------------------------------------------------------------
// FUSED dual-GCN aggregation + LayerNorm (both branches in one block).
// hw2: z0 = xc@Wgcc (conf branch), z1 = xa@Wgca (adj branch).
// Outputs: conf bf16 (LN w/ gamma1), orig = LN_adj + LN_conf (fp32 + bf16).
// ---------------------------------------------------------------------------
__global__ __launch_bounds__(256)
void gcn2_ln_k(const float* __restrict__ hw2,
               const float* __restrict__ bgcc, const float* __restrict__ bgca,
               const float* __restrict__ lng, const float* __restrict__ lnb,
               uint16_t* __restrict__ conf_hi, uint16_t* __restrict__ conf_lo,
               float* __restrict__ orig_f32,
               uint16_t* __restrict__ orig_hi, uint16_t* __restrict__ orig_lo)
{
    int r = blockIdx.x;
    int n = r >> 3, b = r & 7;
    int i = n >> 5, j = n & 31;
    float degn = grid_deg(i, j);

    int   nbr[5];
    float nrm[5];
    nbr[0] = n;                       nrm[0] = 1.f / degn;
    nbr[1] = (i > 0)  ? n - 32 : n;
    nbr[2] = (i < 31) ? n + 32 : n;
    nbr[3] = (j > 0)  ? n - 1  : n;
    nbr[4] = (j < 31) ? n + 1  : n;
    bool vld[5] = { true, i > 0, i < 31, j > 0, j < 31 };
    #pragma unroll
    for (int t = 1; t < 5; t++) {
        int m = nbr[t];
        float degm = grid_deg(m >> 5, m & 31);
        nrm[t] = vld[t] ? rsqrtf(degm * degn) : 0.f;
    }

    int c = threadIdx.x;
    const float* hwA = hw2 + (size_t)MROWS * CDIM;   // adj branch (z1)

    // ---- adj branch: aggregate + LN (gamma0/beta0)
    float accA = bgca[c];
    #pragma unroll
    for (int t = 0; t < 5; t++)
        accA += nrm[t] * hwA[((size_t)nbr[t] * BSZ + b) * CDIM + c];
    float meanA = bsum256(accA) * (1.f / CDIM);
    float dA = accA - meanA;
    float varA = bsum256(dA * dA) * (1.f / CDIM);
    float a = dA * rsqrtf(varA + EPSLN) * lng[c] + lnb[c];

    // ---- conf branch: aggregate + LN (gamma1/beta1)
    float accC = bgcc[c];
    #pragma unroll
    for (int t = 0; t < 5; t++)
        accC += nrm[t] * hw2[((size_t)nbr[t] * BSZ + b) * CDIM + c];
    float meanC = bsum256(accC) * (1.f / CDIM);
    float dC = accC - meanC;
    float varC = bsum256(dC * dC) * (1.f / CDIM);
    float cf = dC * rsqrtf(varC + EPSLN) * lng[CDIM + c] + lnb[CDIM + c];

    size_t idx = (size_t)r * CDIM + c;
    uint32_t h, l;
    bf16_split(cf, h, l);
    conf_hi[idx] = (uint16_t)h; conf_lo[idx] = (uint16_t)l;

    float o2 = a + cf;
    orig_f32[idx] = o2;
    bf16_split(o2, h, l);
    orig_hi[idx] = (uint16_t)h; orig_lo[idx] = (uint16_t)l;
}

// ---------------------------------------------------------------------------
// Final residual LayerNorm, writing image layout out[b,c,n]
// ---------------------------------------------------------------------------
__global__ __launch_bounds__(256)
void ln_out_k(const float* __restrict__ in, const float* __restrict__ gamma,
              const float* __restrict__ beta, float* __restrict__ outp)
{
    int r = blockIdx.x;
    int n = r >> 3, b = r & 7;
    int c = threadIdx.x;
    float v = in[(size_t)r * CDIM + c];
    float mean = bsum256(v) * (1.f / CDIM);
    float d = v - mean;
    float var = bsum256(d * d) * (1.f / CDIM);
    outp[(size_t)b * (CDIM * NDIM) + (size_t)c * NDIM + n] =
        d * rsqrtf(var + EPSLN) * gamma[c] + beta[c];
}

// ---------------------------------------------------------------------------
// GATv2 aggregation for ONE hypothesis (pointers pre-offset on host).
// Per-warp private partial sums + 8-way tree reduce.
// ---------------------------------------------------------------------------
__global__ __launch_bounds__(256)
void gat_k(const float* __restrict__ base, const float* __restrict__ att,
           const float* __restrict__ gbias, float* __restrict__ outp)
{
    __shared__ float sacc[NHEAD][CDIM];

    int r = blockIdx.x;
    int n = r >> 3, b = r & 7;
    int i = n >> 5, j = n & 31;

    int nbr[5];
    nbr[0] = n;
    nbr[1] = (i > 0)  ? n - 32 : n;
    nbr[2] = (i < 31) ? n + 32 : n;
    nbr[3] = (j > 0)  ? n - 1  : n;
    nbr[4] = (j < 31) ? n + 1  : n;
    bool vld[5] = { true, i > 0, i < 31, j > 0, j < 31 };

    int wid = threadIdx.x >> 5, lane = threadIdx.x & 31;
    const float* xrp  = base + ((size_t)n * BSZ + b) * NLR + HC + wid * CDIM + lane;
    const float* attp = att + wid * CDIM + lane;

    float xrv[8], attv[8];
    #pragma unroll
    for (int t = 0; t < 8; t++) { xrv[t] = xrp[32 * t]; attv[t] = attp[32 * t]; }

    float xlv[5][8], logit[5];
    #pragma unroll
    for (int m = 0; m < 5; m++) {
        const float* xlp = base + ((size_t)nbr[m] * BSZ + b) * NLR + wid * CDIM + lane;
        float s = 0.f;
        #pragma unroll
        for (int t = 0; t < 8; t++) {
            float v = xlp[32 * t];
            xlv[m][t] = v;
            float e = v + xrv[t];
            e = e > 0.f ? e : NEG * e;
            s += e * attv[t];
        }
        #pragma unroll
        for (int o = 16; o > 0; o >>= 1) s += __shfl_xor_sync(0xffffffffu, s, o);
        logit[m] = vld[m] ? s : -1e30f;
    }

    float mx = logit[0];
    #pragma unroll
    for (int m = 1; m < 5; m++) mx = fmaxf(mx, logit[m]);
    float alpha[5], ssum = 0.f;
    #pragma unroll
    for (int m = 0; m < 5; m++) { alpha[m] = expf(logit[m] - mx); ssum += alpha[m]; }
    float scale = 1.f / (ssum * NHEAD);

    #pragma unroll
    for (int t = 0; t < 8; t++) {
        float o = 0.f;
        #pragma unroll
        for (int m = 0; m < 5; m++) o += alpha[m] * xlv[m][t];
        sacc[wid][lane + 32 * t] = o * scale;
    }
    __syncthreads();

    int c = threadIdx.x;
    float s = sacc[0][c];
    #pragma unroll
    for (int w = 1; w < NHEAD; w++) s += sacc[w][c];
    outp[(size_t)b * (CDIM * NDIM) + (size_t)c * NDIM + n] = s + gbias[c];
}

// ---------------------------------------------------------------------------
// Host
// ---------------------------------------------------------------------------
static void gemm(const uint16_t* Ah, const uint16_t* Al,
                 const uint16_t* Bh, const uint16_t* Bl, int ldb,
                 const float* bias, const float* res,
                 float* C, uint16_t* Chi, uint16_t* Clo,
                 uint16_t* C2hi, uint16_t* C2lo,
                 int M, int N, int K, int act, int Z,
                 size_t zA, size_t zB, size_t zBias, size_t zC, size_t zRes)
{
    cudaFuncSetAttribute(gemm_k, cudaFuncAttributeMaxDynamicSharedMemorySize, GSMEM_BYTES);
    gemm_k<<<dim3(N / 128, M / 64, Z), 256, GSMEM_BYTES>>>(
        Ah, Al, Bh, Bl, bias, res, C, Chi, Clo, C2hi, C2lo,
        M, N, K, ldb, act, zA, zB, zBias, zC, zRes);
}

extern "C" void kernel_launch(void* const* d_in, const int* in_sizes, int n_in,
                              void* d_out, int out_size)
{
    const float* x    = (const float*)d_in[0];
    // d_in[1] = edge_index (int64) — fixed 32x32 grid; computed analytically.
    const float* Wp   = (const float*)d_in[2];
    const float* bp   = (const float*)d_in[3];
    const float* Wm1  = (const float*)d_in[4];
    const float* bm1  = (const float*)d_in[5];
    const float* Wm2  = (const float*)d_in[6];
    const float* bm2  = (const float*)d_in[7];
    const float* Wgca = (const float*)d_in[8];
    const float* bgca = (const float*)d_in[9];
    const float* Wgcc = (const float*)d_in[10];
    const float* bgcc = (const float*)d_in[11];
    const float* Wi1  = (const float*)d_in[12];
    const float* bi1  = (const float*)d_in[13];
    const float* Wi2  = (const float*)d_in[14];
    const float* bi2  = (const float*)d_in[15];
    const float* Wl   = (const float*)d_in[16];
    const float* bl   = (const float*)d_in[17];
    const float* Wr   = (const float*)d_in[18];
    const float* br   = (const float*)d_in[19];
    const float* att  = (const float*)d_in[20];
    const float* gbia = (const float*)d_in[21];
    const float* Wf1  = (const float*)d_in[22];
    const float* bf1  = (const float*)d_in[23];
    const float* Wf2  = (const float*)d_in[24];
    const float* bf2  = (const float*)d_in[25];
    const float* lng  = (const float*)d_in[26];
    const float* lnb  = (const float*)d_in[27];
    float* out = (float*)d_out;

    float *pNode, *pOrig, *pTmp, *pTmp2, *pXlr, *pBlr;
    cudaGetSymbolAddress((void**)&pNode, g_node);
    cudaGetSymbolAddress((void**)&pOrig, g_orig);
    cudaGetSymbolAddress((void**)&pTmp,  g_tmp);
    cudaGetSymbolAddress((void**)&pTmp2, g_tmp2);
    cudaGetSymbolAddress((void**)&pXlr,  g_xlr);
    cudaGetSymbolAddress((void**)&pBlr,  g_blr);

    uint16_t *X0h,*X0l,*Nodeh,*Nodel,*Hidh,*Hidl,*Gateh,*Gatel,*Confh,*Confl;
    uint16_t *Origh,*Origl,*Hid3h,*Hid3l,*Feat3h,*Feat3l;
    cudaGetSymbolAddress((void**)&X0h, bX0h);     cudaGetSymbolAddress((void**)&X0l, bX0l);
    cudaGetSymbolAddress((void**)&Nodeh, bNodeh); cudaGetSymbolAddress((void**)&Nodel, bNodel);
    cudaGetSymbolAddress((void**)&Hidh, bHidh);   cudaGetSymbolAddress((void**)&Hidl, bHidl);
    cudaGetSymbolAddress((void**)&Gateh, bGateh); cudaGetSymbolAddress((void**)&Gatel, bGatel);
    cudaGetSymbolAddress((void**)&Confh, bConfh); cudaGetSymbolAddress((void**)&Confl, bConfl);
    cudaGetSymbolAddress((void**)&Origh, bOrigh); cudaGetSymbolAddress((void**)&Origl, bOrigl);
    cudaGetSymbolAddress((void**)&Hid3h, bHid3h); cudaGetSymbolAddress((void**)&Hid3l, bHid3l);
    cudaGetSymbolAddress((void**)&Feat3h, bFeat3h); cudaGetSymbolAddress((void**)&Feat3l, bFeat3l);

    uint16_t *Wph,*Wpl,*Wm1h,*Wm1l,*Wm2h,*Wm2l,*Gh,*Gl,*Wi1h,*Wi1l,*Wi2h,*Wi2l;
    uint16_t *LRh,*LRl,*Wf1h,*Wf1l,*Wf2h,*Wf2l;
    cudaGetSymbolAddress((void**)&Wph, wWph);   cudaGetSymbolAddress((void**)&Wpl, wWpl);
    cudaGetSymbolAddress((void**)&Wm1h, wWm1h); cudaGetSymbolAddress((void**)&Wm1l, wWm1l);
    cudaGetSymbolAddress((void**)&Wm2h, wWm2h); cudaGetSymbolAddress((void**)&Wm2l, wWm2l);
    cudaGetSymbolAddress((void**)&Gh, wGh);     cudaGetSymbolAddress((void**)&Gl, wGl);
    cudaGetSymbolAddress((void**)&Wi1h, wWi1h); cudaGetSymbolAddress((void**)&Wi1l, wWi1l);
    cudaGetSymbolAddress((void**)&Wi2h, wWi2h); cudaGetSymbolAddress((void**)&Wi2l, wWi2l);
    cudaGetSymbolAddress((void**)&LRh, wLRh);   cudaGetSymbolAddress((void**)&LRl, wLRl);
    cudaGetSymbolAddress((void**)&Wf1h, wWf1h); cudaGetSymbolAddress((void**)&Wf1l, wWf1l);
    cudaGetSymbolAddress((void**)&Wf2h, wWf2h); cudaGetSymbolAddress((void**)&Wf2l, wWf2l);

    const size_t OUTSZ = (size_t)BSZ * CDIM * NDIM;

    // 0. ALL weight conversions in ONE launch (15 jobs incl. Wf1/Wf2)
    ConvJobs jobs;
    int ji = 0;
    auto addjob = [&](const float* s, uint16_t* h, uint16_t* l, int N, int LD, int off, int total) {
        jobs.j[ji++] = ConvJob{ s, h, l, N, LD, off, total / 4 };
    };
    addjob(Wp,   Wph,  Wpl,  CDIM, CDIM, 0, CDIM * CDIM);
    addjob(Wm1,  Wm1h, Wm1l, HIDD, HIDD, 0, CDIM * HIDD);
    addjob(Wm2,  Wm2h, Wm2l, CDIM, CDIM, 0, HIDD * CDIM);
    addjob(Wgcc, Gh,               Gl,               CDIM, CDIM, 0, CDIM * CDIM);
    addjob(Wgca, Gh + CDIM * CDIM, Gl + CDIM * CDIM, CDIM, CDIM, 0, CDIM * CDIM);
    addjob(Wi1,  Wi1h, Wi1l, HIDD, HIDD, 0, NHYP * CDIM * HIDD);
    addjob(Wi2,  Wi2h, Wi2l, CDIM, CDIM, 0, NHYP * HIDD * CDIM);
    for (int z = 0; z < NHYP; z++) {
        size_t ws = (size_t)z * CDIM * HC, wd = (size_t)z * CDIM * NLR;
        addjob(Wl + ws, LRh + wd, LRl + wd, HC, NLR, 0,  CDIM * HC);
        addjob(Wr + ws, LRh + wd, LRl + wd, HC, NLR, HC, CDIM * HC);
    }
    addjob(Wf1, Wf1h, Wf1l, FFD,  FFD,  0, CDIM * FFD);
    addjob(Wf2, Wf2h, Wf2l, CDIM, CDIM, 0, FFD * CDIM);
    convert_all_k<<<dim3(512, NJOBS), 256>>>(jobs);
    blr_fill_k<<<NHYP, 256>>>(bl, br, pBlr);

    // 1. x -> X0 (bf16 hi/lo), vectorized u32 stores
    transpose_in_k<<<dim3(NDIM / 32, CDIM / 32, BSZ), dim3(16, 32)>>>(x, X0h, X0l);

    // 2. node = X0 @ Wp + bp  (fp32 + bf16)
    gemm(X0h, X0l, Wph, Wpl, CDIM, bp, nullptr,
         pNode, Nodeh, Nodel, nullptr, nullptr, MROWS, CDIM, CDIM, 3, 1, 0,0,0,0,0);

    // 3. hid = relu(node@Wm1+bm1); gate fused into Wm2 epilogue
    gemm(Nodeh, Nodel, Wm1h, Wm1l, HIDD, bm1, nullptr,
         nullptr, Hidh, Hidl, nullptr, nullptr, MROWS, HIDD, CDIM, 1, 1, 0,0,0,0,0);
    gemm(Hidh, Hidl, Wm2h, Wm2l, CDIM, bm2, pNode,
         nullptr, Gateh, Gatel, Gateh + (size_t)MROWS * CDIM, Gatel + (size_t)MROWS * CDIM,
         MROWS, CDIM, HIDD, 2, 1, 0,0,0,0,0);

    // 4. GCN GEMMs batched (z0: xc@Wgcc, z1: xa@Wgca), then ONE fused dual-LN
    gemm(Gateh, Gatel, Gh, Gl, CDIM, nullptr, nullptr,
         pTmp2, nullptr, nullptr, nullptr, nullptr, MROWS, CDIM, CDIM, 0, 2,
         (size_t)MROWS * CDIM, (size_t)CDIM * CDIM, 0, (size_t)MROWS * CDIM, 0);
    gcn2_ln_k<<<MROWS, CDIM>>>(pTmp2, bgcc, bgca, lng, lnb,
                               Confh, Confl, pOrig, Origh, Origl);

    // 5. hypotheses: interv chain z-batched; LR + gat interleaved per hyp so
    //    the single xlr buffer stays L2-hot between producer/consumer
    gemm(Confh, Confl, Wi1h, Wi1l, HIDD, bi1, nullptr,
         nullptr, Hid3h, Hid3l, nullptr, nullptr, MROWS, HIDD, CDIM, 1, NHYP,
         0, (size_t)CDIM * HIDD, HIDD, (size_t)MROWS * HIDD, 0);
    gemm(Hid3h, Hid3l, Wi2h, Wi2l, CDIM, bi2, pOrig,
         nullptr, Feat3h, Feat3l, nullptr, nullptr, MROWS, CDIM, HIDD, 4, NHYP,
         (size_t)MROWS * HIDD, (size_t)HIDD * CDIM, CDIM, (size_t)MROWS * CDIM, 0);
    for (int h = 0; h < NHYP; h++) {
        gemm(Feat3h + (size_t)h * MROWS * CDIM, Feat3l + (size_t)h * MROWS * CDIM,
             LRh + (size_t)h * CDIM * NLR, LRl + (size_t)h * CDIM * NLR, NLR,
             pBlr + (size_t)h * NLR, nullptr,
             pXlr, nullptr, nullptr, nullptr, nullptr, MROWS, NLR, CDIM, 0, 1,
             0, 0, 0, 0, 0);
        gat_k<<<MROWS, 256>>>(pXlr, att + (size_t)h * HC,
                              gbia + (size_t)h * CDIM, out + (size_t)h * OUTSZ);
    }

    // 6. FFN + residual LN -> output slot 3
    gemm(Origh, Origl, Wf1h, Wf1l, FFD, bf1, nullptr,
         nullptr, Hidh, Hidl, nullptr, nullptr, MROWS, FFD, CDIM, 1, 1, 0,0,0,0,0);
    gemm(Hidh, Hidl, Wf2h, Wf2l, CDIM, bf2, pOrig,
         pTmp, nullptr, nullptr, nullptr, nullptr, MROWS, CDIM, FFD, 0, 1, 0,0,0,0,0);
    ln_out_k<<<MROWS, CDIM>>>(pTmp, lng + 2 * CDIM, lnb + 2 * CDIM, out + 3 * OUTSZ);
}